// round 3
// baseline (speedup 1.0000x reference)
#include <cuda_runtime.h>
#include <cuda_bf16.h>
#include <math.h>
#include <stdint.h>

// Problem constants: B=8, N=4096, C=1024, H=16, dh=64
#define BB 8
#define NN 4096
#define CC 1024
#define HH 16
#define DH 64
#define M_ROWS (BB * NN)          // 32768
#define QKV_COLS (3 * CC)         // 3072

// ---------------- static scratch (no runtime allocation allowed) -------------
__device__ __align__(128) float g_Y[(size_t)M_ROWS * QKV_COLS];   // qkv: [32768, 3072]
__device__ __align__(128) float g_Z[(size_t)M_ROWS * CC];         // attn@v reshaped: [32768, 1024]
__device__ __align__(128) float g_Spart[(size_t)BB * HH * 8 * DH * DH]; // partial grams
__device__ __align__(128) float g_attn[(size_t)BB * HH * DH * DH];      // softmaxed attn
__device__ __align__(128) float g_sumsq[BB * 2 * CC];                   // per-(b,col) sumsq q,k

// ---------------------------------------------------------------------------
// bf16x3 emulated-fp32 tensor-core GEMM.
// C[M,N] = A[M,K] @ B[K,N] (+bias), A,B,C fp32 row-major.
// Split x = hi + lo (bf16 each); C = AhBh + AhBl + AlBh with f32 accum.
// Tile 128x128x32, 256 threads (8 warps, 4(M) x 2(N)), warp tile 32x64,
// mma.sync.aligned.m16n8k16.row.col.f32.bf16.bf16.f32.
// ---------------------------------------------------------------------------
#define LDSK 40   // smem row stride in bf16 halves (20 words) -> conflict-free frags

__device__ __forceinline__ void mma_bf16(float* c, const uint32_t* a, const uint32_t* b) {
  asm volatile(
      "mma.sync.aligned.m16n8k16.row.col.f32.bf16.bf16.f32 "
      "{%0,%1,%2,%3}, {%4,%5,%6,%7}, {%8,%9}, {%0,%1,%2,%3};\n"
      : "+f"(c[0]), "+f"(c[1]), "+f"(c[2]), "+f"(c[3])
      : "r"(a[0]), "r"(a[1]), "r"(a[2]), "r"(a[3]), "r"(b[0]), "r"(b[1]));
}

__device__ __forceinline__ void cvt_hilo(float x, __nv_bfloat16& h, __nv_bfloat16& l) {
  h = __float2bfloat16_rn(x);
  l = __float2bfloat16_rn(x - __bfloat162float(h));
}

__global__ __launch_bounds__(256) void gemm_bf16x3(
    const float* __restrict__ A, const float* __restrict__ B,
    float* __restrict__ C, const float* __restrict__ bias,
    int M, int N, int K) {
  constexpr int BM = 128, BN = 128, BK = 32;
  __shared__ __nv_bfloat16 AsH[BM][LDSK];
  __shared__ __nv_bfloat16 AsL[BM][LDSK];
  __shared__ __nv_bfloat16 BsH[BN][LDSK];   // transposed: [n][k]
  __shared__ __nv_bfloat16 BsL[BN][LDSK];

  const int tid = threadIdx.x;
  const int lane = tid & 31;
  const int w = tid >> 5;
  const int wm = w & 3;          // 4 warp rows of 32
  const int wn = w >> 2;         // 2 warp cols of 64
  const int g = lane >> 2;       // 0..7
  const int tig = lane & 3;      // 0..3
  const size_t bm = (size_t)blockIdx.y * BM;
  const size_t bn = (size_t)blockIdx.x * BN;

  float acc[2][8][4];
#pragma unroll
  for (int mi = 0; mi < 2; ++mi)
#pragma unroll
    for (int ni = 0; ni < 8; ++ni)
#pragma unroll
      for (int j = 0; j < 4; ++j) acc[mi][ni][j] = 0.0f;

  for (int k0 = 0; k0 < K; k0 += BK) {
    // --- load + split A tile: 128 rows x 32 k (8 float4 per row) ---
#pragma unroll
    for (int i = 0; i < 4; ++i) {
      int lin = tid + i * 256;          // 0..1023
      int r = lin >> 3;
      int c4 = (lin & 7) << 2;
      float4 v = *(const float4*)(A + (bm + r) * K + k0 + c4);
      __nv_bfloat16 h0, h1, h2, h3, l0, l1, l2, l3;
      cvt_hilo(v.x, h0, l0); cvt_hilo(v.y, h1, l1);
      cvt_hilo(v.z, h2, l2); cvt_hilo(v.w, h3, l3);
      *(__nv_bfloat162*)&AsH[r][c4]     = __nv_bfloat162(h0, h1);
      *(__nv_bfloat162*)&AsH[r][c4 + 2] = __nv_bfloat162(h2, h3);
      *(__nv_bfloat162*)&AsL[r][c4]     = __nv_bfloat162(l0, l1);
      *(__nv_bfloat162*)&AsL[r][c4 + 2] = __nv_bfloat162(l2, l3);
    }
    // --- load + split + transpose B tile: 32 k-rows x 128 n ---
#pragma unroll
    for (int i = 0; i < 4; ++i) {
      int lin = tid + i * 256;          // 0..1023
      int kr = lin >> 5;                // 0..31
      int c4 = (lin & 31) << 2;         // 0..124
      float4 v = *(const float4*)(B + (size_t)(k0 + kr) * N + bn + c4);
      __nv_bfloat16 h, l;
      cvt_hilo(v.x, h, l); BsH[c4 + 0][kr] = h; BsL[c4 + 0][kr] = l;
      cvt_hilo(v.y, h, l); BsH[c4 + 1][kr] = h; BsL[c4 + 1][kr] = l;
      cvt_hilo(v.z, h, l); BsH[c4 + 2][kr] = h; BsL[c4 + 2][kr] = l;
      cvt_hilo(v.w, h, l); BsH[c4 + 3][kr] = h; BsL[c4 + 3][kr] = l;
    }
    __syncthreads();

#pragma unroll
    for (int kk = 0; kk < BK; kk += 16) {
      uint32_t aH[2][4], aL[2][4], bH[8][2], bL[8][2];
      const int kc = kk + 2 * tig;
#pragma unroll
      for (int mi = 0; mi < 2; ++mi) {
        int row = wm * 32 + mi * 16 + g;
        aH[mi][0] = *(const uint32_t*)&AsH[row][kc];
        aH[mi][1] = *(const uint32_t*)&AsH[row + 8][kc];
        aH[mi][2] = *(const uint32_t*)&AsH[row][kc + 8];
        aH[mi][3] = *(const uint32_t*)&AsH[row + 8][kc + 8];
        aL[mi][0] = *(const uint32_t*)&AsL[row][kc];
        aL[mi][1] = *(const uint32_t*)&AsL[row + 8][kc];
        aL[mi][2] = *(const uint32_t*)&AsL[row][kc + 8];
        aL[mi][3] = *(const uint32_t*)&AsL[row + 8][kc + 8];
      }
#pragma unroll
      for (int ni = 0; ni < 8; ++ni) {
        int col = wn * 64 + ni * 8 + g;
        bH[ni][0] = *(const uint32_t*)&BsH[col][kc];
        bH[ni][1] = *(const uint32_t*)&BsH[col][kc + 8];
        bL[ni][0] = *(const uint32_t*)&BsL[col][kc];
        bL[ni][1] = *(const uint32_t*)&BsL[col][kc + 8];
      }
#pragma unroll
      for (int mi = 0; mi < 2; ++mi)
#pragma unroll
        for (int ni = 0; ni < 8; ++ni) {
          mma_bf16(acc[mi][ni], aH[mi], bH[ni]);
          mma_bf16(acc[mi][ni], aH[mi], bL[ni]);
          mma_bf16(acc[mi][ni], aL[mi], bH[ni]);
        }
    }
    __syncthreads();
  }

  // --- epilogue ---
#pragma unroll
  for (int mi = 0; mi < 2; ++mi) {
    int row0 = (int)bm + wm * 32 + mi * 16 + g;
#pragma unroll
    for (int ni = 0; ni < 8; ++ni) {
      int col0 = (int)bn + wn * 64 + ni * 8 + 2 * tig;
      float bv0 = 0.0f, bv1 = 0.0f;
      if (bias) { bv0 = bias[col0]; bv1 = bias[col0 + 1]; }
      float2 o0 = make_float2(acc[mi][ni][0] + bv0, acc[mi][ni][1] + bv1);
      float2 o1 = make_float2(acc[mi][ni][2] + bv0, acc[mi][ni][3] + bv1);
      *(float2*)(C + (size_t)row0 * N + col0) = o0;
      *(float2*)(C + (size_t)(row0 + 8) * N + col0) = o1;
    }
  }
}

// ---------------------------------------------------------------------------
// K2: per-batch column sum-of-squares over the token axis for q,k columns.
// ---------------------------------------------------------------------------
__global__ __launch_bounds__(256) void sumsq_kernel() {
  const int b = blockIdx.y;
  const int col = blockIdx.x * 64 + (threadIdx.x & 63);
  const int part = threadIdx.x >> 6;   // 0..3
  const float* base = g_Y + (size_t)b * NN * QKV_COLS + col;
  float s = 0.0f;
  for (int n = part; n < NN; n += 4) {
    float v = base[(size_t)n * QKV_COLS];
    s += v * v;
  }
  __shared__ float red[256];
  red[threadIdx.x] = s;
  __syncthreads();
  if (part == 0) {
    int t = threadIdx.x;
    g_sumsq[b * 2048 + col] = red[t] + red[t + 64] + red[t + 128] + red[t + 192];
  }
}

// ---------------------------------------------------------------------------
// K3: partial gram S[d][e] = sum_n q[d,n]*k[e,n] per (b,h), 8 token segments.
// ---------------------------------------------------------------------------
__global__ __launch_bounds__(256) void gram_kernel() {
  const int seg = blockIdx.x;          // 0..7
  const int bh = blockIdx.y;           // 0..127
  const int b = bh >> 4, h = bh & 15;
  __shared__ float qs[32][64];
  __shared__ float ks[32][64];
  const int tid = threadIdx.x;
  const int tx = tid & 15, ty = tid >> 4;
  float acc[4][4] = {};

  const float* Yq = g_Y + (size_t)(b * NN + seg * 512) * QKV_COLS + h * DH;
  const float* Yk = Yq + CC;

  for (int ch = 0; ch < 16; ++ch) {
#pragma unroll
    for (int i = 0; i < 2; ++i) {
      int lin = tid + i * 256;
      int r = lin >> 4;
      int c4 = (lin & 15) << 2;
      size_t off = (size_t)(ch * 32 + r) * QKV_COLS + c4;
      *(float4*)&qs[r][c4] = *(const float4*)(Yq + off);
      *(float4*)&ks[r][c4] = *(const float4*)(Yk + off);
    }
    __syncthreads();
#pragma unroll
    for (int r = 0; r < 32; ++r) {
      float4 qa = *(float4*)&qs[r][ty * 4];
      float4 ka = *(float4*)&ks[r][tx * 4];
      float qv[4] = {qa.x, qa.y, qa.z, qa.w};
      float kv[4] = {ka.x, ka.y, ka.z, ka.w};
#pragma unroll
      for (int i = 0; i < 4; ++i)
#pragma unroll
        for (int j = 0; j < 4; ++j)
          acc[i][j] += qv[i] * kv[j];
    }
    __syncthreads();
  }

  float* Sout = g_Spart + (size_t)(bh * 8 + seg) * (DH * DH);
#pragma unroll
  for (int i = 0; i < 4; ++i)
#pragma unroll
    for (int j = 0; j < 4; ++j)
      Sout[(ty * 4 + i) * DH + tx * 4 + j] = acc[i][j];
}

// ---------------------------------------------------------------------------
// K3b: reduce partial grams, scale by 1/(|q||k|)*temp, softmax over e.
// ---------------------------------------------------------------------------
__global__ __launch_bounds__(256) void softmax_kernel(const float* __restrict__ temp) {
  const int bh = blockIdx.x;
  const int b = bh >> 4, h = bh & 15;
  __shared__ float S[64][65];
  __shared__ float nqv[64], nkv[64];
  const int tid = threadIdx.x;

  if (tid < 64) {
    nqv[tid] = fmaxf(sqrtf(g_sumsq[b * 2048 + h * DH + tid]), 1e-12f);
    nkv[tid] = fmaxf(sqrtf(g_sumsq[b * 2048 + CC + h * DH + tid]), 1e-12f);
  }
  __syncthreads();

  const float tp = temp[h];
  for (int idx = tid; idx < DH * DH; idx += 256) {
    float s = 0.0f;
#pragma unroll
    for (int seg = 0; seg < 8; ++seg)
      s += g_Spart[(size_t)(bh * 8 + seg) * (DH * DH) + idx];
    int d = idx >> 6, e = idx & 63;
    S[d][e] = s / (nqv[d] * nkv[e]) * tp;
  }
  __syncthreads();

  if (tid < 64) {
    int d = tid;
    float m = -3.402823466e38f;
    for (int e = 0; e < 64; ++e) m = fmaxf(m, S[d][e]);
    float sum = 0.0f;
    for (int e = 0; e < 64; ++e) {
      float ex = expf(S[d][e] - m);
      S[d][e] = ex;
      sum += ex;
    }
    float inv = 1.0f / sum;
    float* Ao = g_attn + (size_t)bh * (DH * DH) + d * DH;
    for (int e = 0; e < 64; ++e) Ao[e] = S[d][e] * inv;
  }
}

// ---------------------------------------------------------------------------
// K4: Z[bn, h*64+d] = sum_e attn[b,h,d,e] * v[b,h,e,n].
// ---------------------------------------------------------------------------
__global__ __launch_bounds__(256) void attnv_kernel() {
  const int bh = blockIdx.y;
  const int b = bh >> 4, h = bh & 15;
  const int n = blockIdx.x * 256 + threadIdx.x;
  __shared__ float As[64][64];
  const int tid = threadIdx.x;

  const float* Ag = g_attn + (size_t)bh * (DH * DH);
#pragma unroll
  for (int i = 0; i < 4; ++i) {
    int lin = tid + i * 256;
    *(float4*)&As[lin >> 4][(lin & 15) << 2] = *(const float4*)(Ag + lin * 4);
  }
  __syncthreads();

  const float* v = g_Y + (size_t)(b * NN + n) * QKV_COLS + 2 * CC + h * DH;
  float z[64];
#pragma unroll
  for (int d = 0; d < 64; ++d) z[d] = 0.0f;

#pragma unroll
  for (int c = 0; c < 4; ++c) {
    float4 v0 = *(const float4*)(v + c * 16 + 0);
    float4 v1 = *(const float4*)(v + c * 16 + 4);
    float4 v2 = *(const float4*)(v + c * 16 + 8);
    float4 v3 = *(const float4*)(v + c * 16 + 12);
#pragma unroll
    for (int d = 0; d < 64; ++d) {
      const float4* Ad = (const float4*)&As[d][c * 16];
      float4 a0 = Ad[0], a1 = Ad[1], a2 = Ad[2], a3 = Ad[3];
      float s = a0.x * v0.x + a0.y * v0.y + a0.z * v0.z + a0.w * v0.w;
      s += a1.x * v1.x + a1.y * v1.y + a1.z * v1.z + a1.w * v1.w;
      s += a2.x * v2.x + a2.y * v2.y + a2.z * v2.z + a2.w * v2.w;
      s += a3.x * v3.x + a3.y * v3.y + a3.z * v3.z + a3.w * v3.w;
      z[d] += s;
    }
  }

  float* zo = g_Z + (size_t)(b * NN + n) * CC + h * DH;
#pragma unroll
  for (int d4 = 0; d4 < 16; ++d4)
    *(float4*)(zo + d4 * 4) =
        make_float4(z[d4 * 4], z[d4 * 4 + 1], z[d4 * 4 + 2], z[d4 * 4 + 3]);
}

// ---------------------------------------------------------------------------
extern "C" void kernel_launch(void* const* d_in, const int* in_sizes, int n_in,
                              void* d_out, int out_size) {
  const float* x      = (const float*)d_in[0];  // [8,4096,1024]
  const float* w_qkv  = (const float*)d_in[1];  // [1024,3072]
  const float* temp   = (const float*)d_in[2];  // [16,1,1]
  const float* w_proj = (const float*)d_in[3];  // [1024,1024]
  const float* b_proj = (const float*)d_in[4];  // [1024]
  float* out = (float*)d_out;                   // [8,4096,1024]

  static float* Y = nullptr;
  static float* Z = nullptr;
  if (Y == nullptr) {
    cudaGetSymbolAddress((void**)&Y, g_Y);
    cudaGetSymbolAddress((void**)&Z, g_Z);
  }

  // K1: qkv = x @ w_qkv  -> g_Y [32768, 3072]   (bf16x3 tensor cores)
  gemm_bf16x3<<<dim3(QKV_COLS / 128, M_ROWS / 128), 256>>>(
      x, w_qkv, Y, nullptr, M_ROWS, QKV_COLS, CC);

  // K2: column sum-of-squares for q,k (normalization folded into softmax)
  sumsq_kernel<<<dim3(32, BB), 256>>>();

  // K3: raw grams q.k^T per (b,h), 8 token segments
  gram_kernel<<<dim3(8, BB * HH), 256>>>();

  // K3b: reduce segments, scale by 1/(|q||k|)*temp, softmax
  softmax_kernel<<<BB * HH, 256>>>(temp);

  // K4: Z = attn @ v, written in [B,N,C] layout
  attnv_kernel<<<dim3(NN / 256, BB * HH), 256>>>();

  // K5: out = Z @ w_proj + b_proj   (bf16x3 tensor cores)
  gemm_bf16x3<<<dim3(CC / 128, M_ROWS / 128), 256>>>(
      Z, w_proj, out, b_proj, M_ROWS, CC, CC);
}

// round 5
// speedup vs baseline: 1.2666x; 1.2666x over previous
#include <cuda_runtime.h>
#include <cuda_bf16.h>
#include <math.h>
#include <stdint.h>

// Problem constants: B=8, N=4096, C=1024, H=16, dh=64
#define BB 8
#define NN 4096
#define CC 1024
#define HH 16
#define DH 64
#define M_ROWS (BB * NN)          // 32768
#define QKV_COLS (3 * CC)         // 3072

// ---------------- static scratch (no runtime allocation allowed) -------------
__device__ __align__(128) float g_Y[(size_t)M_ROWS * QKV_COLS];   // qkv: [32768, 3072]
__device__ __align__(128) float g_Z[(size_t)M_ROWS * CC];         // attn@v: [32768, 1024]
__device__ __align__(128) float g_Spart[(size_t)BB * HH * 8 * DH * DH];
__device__ __align__(128) float g_attn[(size_t)BB * HH * DH * DH];
__device__ __align__(128) float g_sumsq[BB * 2 * CC];

// ---------------------------------------------------------------------------
// K1/K5: fp32 SGEMM, double-buffered. C[M,N] = A[M,K] @ B[K,N] (+bias).
// 128x128x16 tile, 256 threads, 8x8 register tile. Two smem stages; LDG for
// tile k+1 overlaps compute of tile k; one __syncthreads per tile.
// ---------------------------------------------------------------------------
__global__ __launch_bounds__(256, 2) void sgemm_db(
    const float* __restrict__ A, const float* __restrict__ B,
    float* __restrict__ C, const float* __restrict__ bias,
    int M, int N, int K) {
  constexpr int BM = 128, BN = 128, BK = 16;
  __shared__ float As[2][BK][BM];   // transposed A tile: [k][m]
  __shared__ float Bs[2][BK][BN];   // [k][n]

  const int tid = threadIdx.x;
  const int tx = tid & 15;          // 16 thread cols
  const int ty = tid >> 4;          // 16 thread rows
  const size_t bm = (size_t)blockIdx.y * BM;
  const size_t bn = (size_t)blockIdx.x * BN;

  // LDG slots: A tile = 512 float4 (128 rows x 4), B tile = 512 float4 (16 x 32).
  const int sa0 = tid, sa1 = tid + 256;
  const int ar0 = sa0 >> 2, ac0 = (sa0 & 3) << 2;
  const int ar1 = sa1 >> 2, ac1 = (sa1 & 3) << 2;
  const int br0 = sa0 >> 5, bc0 = (sa0 & 31) << 2;
  const int br1 = sa1 >> 5, bc1 = (sa1 & 31) << 2;

  const float* Ab = A + bm * K;
  const float* Bb = B + bn;

  float acc[8][8] = {};
  float4 av0, av1, bv0, bv1;

  // ---- prologue: load tile 0 into regs, store to stage 0 ----
  av0 = *(const float4*)(Ab + (size_t)ar0 * K + ac0);
  av1 = *(const float4*)(Ab + (size_t)ar1 * K + ac1);
  bv0 = *(const float4*)(Bb + (size_t)br0 * N + bc0);
  bv1 = *(const float4*)(Bb + (size_t)br1 * N + bc1);
  As[0][ac0 + 0][ar0] = av0.x; As[0][ac0 + 1][ar0] = av0.y;
  As[0][ac0 + 2][ar0] = av0.z; As[0][ac0 + 3][ar0] = av0.w;
  As[0][ac1 + 0][ar1] = av1.x; As[0][ac1 + 1][ar1] = av1.y;
  As[0][ac1 + 2][ar1] = av1.z; As[0][ac1 + 3][ar1] = av1.w;
  *(float4*)&Bs[0][br0][bc0] = bv0;
  *(float4*)&Bs[0][br1][bc1] = bv1;
  __syncthreads();

  const int ntiles = K >> 4;
  int buf = 0;
  for (int kt = 0; kt < ntiles; ++kt) {
    const int knext = (kt + 1) << 4;
    const bool more = (kt + 1 < ntiles);
    if (more) {   // prefetch next tile to regs (latency hidden by compute)
      av0 = *(const float4*)(Ab + (size_t)ar0 * K + knext + ac0);
      av1 = *(const float4*)(Ab + (size_t)ar1 * K + knext + ac1);
      bv0 = *(const float4*)(Bb + (size_t)(knext + br0) * N + bc0);
      bv1 = *(const float4*)(Bb + (size_t)(knext + br1) * N + bc1);
    }
#pragma unroll
    for (int kk = 0; kk < BK; ++kk) {
      float af[8], bf[8];
      *(float4*)&af[0] = *(float4*)&As[buf][kk][ty * 8];
      *(float4*)&af[4] = *(float4*)&As[buf][kk][ty * 8 + 4];
      *(float4*)&bf[0] = *(float4*)&Bs[buf][kk][tx * 8];
      *(float4*)&bf[4] = *(float4*)&Bs[buf][kk][tx * 8 + 4];
#pragma unroll
      for (int i = 0; i < 8; ++i)
#pragma unroll
        for (int j = 0; j < 8; ++j)
          acc[i][j] += af[i] * bf[j];
    }
    if (more) {
      const int nb = buf ^ 1;
      As[nb][ac0 + 0][ar0] = av0.x; As[nb][ac0 + 1][ar0] = av0.y;
      As[nb][ac0 + 2][ar0] = av0.z; As[nb][ac0 + 3][ar0] = av0.w;
      As[nb][ac1 + 0][ar1] = av1.x; As[nb][ac1 + 1][ar1] = av1.y;
      As[nb][ac1 + 2][ar1] = av1.z; As[nb][ac1 + 3][ar1] = av1.w;
      *(float4*)&Bs[nb][br0][bc0] = bv0;
      *(float4*)&Bs[nb][br1][bc1] = bv1;
      __syncthreads();
      buf = nb;
    }
  }

  // ---- epilogue ----
  float bvv[8];
  if (bias) {
#pragma unroll
    for (int j = 0; j < 8; ++j) bvv[j] = bias[bn + tx * 8 + j];
  } else {
#pragma unroll
    for (int j = 0; j < 8; ++j) bvv[j] = 0.0f;
  }
#pragma unroll
  for (int i = 0; i < 8; ++i) {
    size_t row = bm + ty * 8 + i;
    float* Crow = C + row * N + bn + tx * 8;
    *(float4*)(Crow + 0) = make_float4(acc[i][0] + bvv[0], acc[i][1] + bvv[1],
                                       acc[i][2] + bvv[2], acc[i][3] + bvv[3]);
    *(float4*)(Crow + 4) = make_float4(acc[i][4] + bvv[4], acc[i][5] + bvv[5],
                                       acc[i][6] + bvv[6], acc[i][7] + bvv[7]);
  }
}

// ---------------------------------------------------------------------------
// K2: per-batch column sum-of-squares over the token axis for q,k columns.
// ---------------------------------------------------------------------------
__global__ __launch_bounds__(256) void sumsq_kernel() {
  const int b = blockIdx.y;
  const int col = blockIdx.x * 64 + (threadIdx.x & 63);
  const int part = threadIdx.x >> 6;   // 0..3
  const float* base = g_Y + (size_t)b * NN * QKV_COLS + col;
  float s = 0.0f;
  for (int n = part; n < NN; n += 4) {
    float v = base[(size_t)n * QKV_COLS];
    s += v * v;
  }
  __shared__ float red[256];
  red[threadIdx.x] = s;
  __syncthreads();
  if (part == 0) {
    int t = threadIdx.x;
    g_sumsq[b * 2048 + col] = red[t] + red[t + 64] + red[t + 128] + red[t + 192];
  }
}

// ---------------------------------------------------------------------------
// K3: partial gram S[d][e] = sum_n q[d,n]*k[e,n] per (b,h), 8 token segments.
// ---------------------------------------------------------------------------
__global__ __launch_bounds__(256) void gram_kernel() {
  const int seg = blockIdx.x;          // 0..7
  const int bh = blockIdx.y;           // 0..127
  const int b = bh >> 4, h = bh & 15;
  __shared__ float qs[32][64];
  __shared__ float ks[32][64];
  const int tid = threadIdx.x;
  const int tx = tid & 15, ty = tid >> 4;
  float acc[4][4] = {};

  const float* Yq = g_Y + (size_t)(b * NN + seg * 512) * QKV_COLS + h * DH;
  const float* Yk = Yq + CC;

  for (int ch = 0; ch < 16; ++ch) {
#pragma unroll
    for (int i = 0; i < 2; ++i) {
      int lin = tid + i * 256;
      int r = lin >> 4;
      int c4 = (lin & 15) << 2;
      size_t off = (size_t)(ch * 32 + r) * QKV_COLS + c4;
      *(float4*)&qs[r][c4] = *(const float4*)(Yq + off);
      *(float4*)&ks[r][c4] = *(const float4*)(Yk + off);
    }
    __syncthreads();
#pragma unroll
    for (int r = 0; r < 32; ++r) {
      float4 qa = *(float4*)&qs[r][ty * 4];
      float4 ka = *(float4*)&ks[r][tx * 4];
      float qv[4] = {qa.x, qa.y, qa.z, qa.w};
      float kv[4] = {ka.x, ka.y, ka.z, ka.w};
#pragma unroll
      for (int i = 0; i < 4; ++i)
#pragma unroll
        for (int j = 0; j < 4; ++j)
          acc[i][j] += qv[i] * kv[j];
    }
    __syncthreads();
  }

  float* Sout = g_Spart + (size_t)(bh * 8 + seg) * (DH * DH);
#pragma unroll
  for (int i = 0; i < 4; ++i)
#pragma unroll
    for (int j = 0; j < 4; ++j)
      Sout[(ty * 4 + i) * DH + tx * 4 + j] = acc[i][j];
}

// ---------------------------------------------------------------------------
// K3b: reduce grams, scale by 1/(|q||k|)*temp, softmax over e.
// ---------------------------------------------------------------------------
__global__ __launch_bounds__(256) void softmax_kernel(const float* __restrict__ temp) {
  const int bh = blockIdx.x;
  const int b = bh >> 4, h = bh & 15;
  __shared__ float S[64][65];
  __shared__ float nqv[64], nkv[64];
  const int tid = threadIdx.x;

  if (tid < 64) {
    nqv[tid] = fmaxf(sqrtf(g_sumsq[b * 2048 + h * DH + tid]), 1e-12f);
    nkv[tid] = fmaxf(sqrtf(g_sumsq[b * 2048 + CC + h * DH + tid]), 1e-12f);
  }
  __syncthreads();

  const float tp = temp[h];
  for (int idx = tid; idx < DH * DH; idx += 256) {
    float s = 0.0f;
#pragma unroll
    for (int seg = 0; seg < 8; ++seg)
      s += g_Spart[(size_t)(bh * 8 + seg) * (DH * DH) + idx];
    int d = idx >> 6, e = idx & 63;
    S[d][e] = s / (nqv[d] * nkv[e]) * tp;
  }
  __syncthreads();

  if (tid < 64) {
    int d = tid;
    float m = -3.402823466e38f;
    for (int e = 0; e < 64; ++e) m = fmaxf(m, S[d][e]);
    float sum = 0.0f;
    for (int e = 0; e < 64; ++e) {
      float ex = expf(S[d][e] - m);
      S[d][e] = ex;
      sum += ex;
    }
    float inv = 1.0f / sum;
    float* Ao = g_attn + (size_t)bh * (DH * DH) + d * DH;
    for (int e = 0; e < 64; ++e) Ao[e] = S[d][e] * inv;
  }
}

// ---------------------------------------------------------------------------
// K4: Z = attn @ v in [B,N,C] layout.
// ---------------------------------------------------------------------------
__global__ __launch_bounds__(256) void attnv_kernel() {
  const int bh = blockIdx.y;
  const int b = bh >> 4, h = bh & 15;
  const int n = blockIdx.x * 256 + threadIdx.x;
  __shared__ float As[64][64];
  const int tid = threadIdx.x;

  const float* Ag = g_attn + (size_t)bh * (DH * DH);
#pragma unroll
  for (int i = 0; i < 4; ++i) {
    int lin = tid + i * 256;
    *(float4*)&As[lin >> 4][(lin & 15) << 2] = *(const float4*)(Ag + lin * 4);
  }
  __syncthreads();

  const float* v = g_Y + (size_t)(b * NN + n) * QKV_COLS + 2 * CC + h * DH;
  float z[64];
#pragma unroll
  for (int d = 0; d < 64; ++d) z[d] = 0.0f;

#pragma unroll
  for (int c = 0; c < 4; ++c) {
    float4 v0 = *(const float4*)(v + c * 16 + 0);
    float4 v1 = *(const float4*)(v + c * 16 + 4);
    float4 v2 = *(const float4*)(v + c * 16 + 8);
    float4 v3 = *(const float4*)(v + c * 16 + 12);
#pragma unroll
    for (int d = 0; d < 64; ++d) {
      const float4* Ad = (const float4*)&As[d][c * 16];
      float4 a0 = Ad[0], a1 = Ad[1], a2 = Ad[2], a3 = Ad[3];
      float s = a0.x * v0.x + a0.y * v0.y + a0.z * v0.z + a0.w * v0.w;
      s += a1.x * v1.x + a1.y * v1.y + a1.z * v1.z + a1.w * v1.w;
      s += a2.x * v2.x + a2.y * v2.y + a2.z * v2.z + a2.w * v2.w;
      s += a3.x * v3.x + a3.y * v3.y + a3.z * v3.z + a3.w * v3.w;
      z[d] += s;
    }
  }

  float* zo = g_Z + (size_t)(b * NN + n) * CC + h * DH;
#pragma unroll
  for (int d4 = 0; d4 < 16; ++d4)
    *(float4*)(zo + d4 * 4) =
        make_float4(z[d4 * 4], z[d4 * 4 + 1], z[d4 * 4 + 2], z[d4 * 4 + 3]);
}

// ---------------------------------------------------------------------------
extern "C" void kernel_launch(void* const* d_in, const int* in_sizes, int n_in,
                              void* d_out, int out_size) {
  const float* x      = (const float*)d_in[0];  // [8,4096,1024]
  const float* w_qkv  = (const float*)d_in[1];  // [1024,3072]
  const float* temp   = (const float*)d_in[2];  // [16,1,1]
  const float* w_proj = (const float*)d_in[3];  // [1024,1024]
  const float* b_proj = (const float*)d_in[4];  // [1024]
  float* out = (float*)d_out;                   // [8,4096,1024]

  static float* Y = nullptr;
  static float* Z = nullptr;
  if (Y == nullptr) {
    cudaGetSymbolAddress((void**)&Y, g_Y);
    cudaGetSymbolAddress((void**)&Z, g_Z);
  }

  // K1: qkv = x @ w_qkv  -> g_Y [32768, 3072]
  sgemm_db<<<dim3(QKV_COLS / 128, M_ROWS / 128), 256>>>(
      x, w_qkv, Y, nullptr, M_ROWS, QKV_COLS, CC);

  // K2: column sum-of-squares for q,k (normalization folded into softmax)
  sumsq_kernel<<<dim3(32, BB), 256>>>();

  // K3: raw grams q.k^T per (b,h), 8 token segments
  gram_kernel<<<dim3(8, BB * HH), 256>>>();

  // K3b: reduce segments, scale by 1/(|q||k|)*temp, softmax
  softmax_kernel<<<BB * HH, 256>>>(temp);

  // K4: Z = attn @ v, written in [B,N,C] layout
  attnv_kernel<<<dim3(NN / 256, BB * HH), 256>>>();

  // K5: out = Z @ w_proj + b_proj
  sgemm_db<<<dim3(CC / 128, M_ROWS / 128), 256>>>(
      Z, w_proj, out, b_proj, M_ROWS, CC, CC);
}

// round 6
// speedup vs baseline: 5.2228x; 4.1234x over previous
#include <cuda_runtime.h>
#include <cuda_fp16.h>
#include <math.h>
#include <stdint.h>

// Problem constants: B=8, N=4096, C=1024, H=16, dh=64
#define BB 8
#define NN 4096
#define CC 1024
#define HH 16
#define DH 64
#define M_ROWS (BB * NN)          // 32768
#define QKV_COLS (3 * CC)         // 3072

// ---------------- static scratch (no runtime allocation allowed) -------------
__device__ __align__(128) float g_Y[(size_t)M_ROWS * QKV_COLS];   // qkv fp32
__device__ __align__(128) float g_Z[(size_t)M_ROWS * CC];         // attn@v fp32
__device__ __align__(128) float g_Spart[(size_t)BB * HH * 8 * DH * DH];
__device__ __align__(128) float g_attn[(size_t)BB * HH * DH * DH];
__device__ __align__(128) float g_sumsq[BB * 2 * CC];
__device__ __align__(128) __half g_Af16[(size_t)M_ROWS * CC];     // activations fp16 [M,K]
__device__ __align__(128) __half g_Wf16[(size_t)QKV_COLS * CC];   // weights^T fp16 [N,K]

// ============================ helpers =======================================
__device__ __forceinline__ uint32_t smem_u32(const void* p) {
  uint32_t a;
  asm("{ .reg .u64 t; cvta.to.shared.u64 t, %1; cvt.u32.u64 %0, t; }" : "=r"(a) : "l"(p));
  return a;
}
__device__ __forceinline__ void cp_async16(uint32_t dst, const void* src) {
  asm volatile("cp.async.cg.shared.global [%0], [%1], 16;" :: "r"(dst), "l"(src));
}
__device__ __forceinline__ void ldsm_x4(uint32_t* r, uint32_t addr) {
  asm volatile("ldmatrix.sync.aligned.m8n8.x4.shared.b16 {%0,%1,%2,%3}, [%4];"
               : "=r"(r[0]), "=r"(r[1]), "=r"(r[2]), "=r"(r[3]) : "r"(addr));
}
__device__ __forceinline__ void mma_f16(float* c, const uint32_t* a, uint32_t b0,
                                        uint32_t b1) {
  asm volatile(
      "mma.sync.aligned.m16n8k16.row.col.f32.f16.f16.f32 "
      "{%0,%1,%2,%3}, {%4,%5,%6,%7}, {%8,%9}, {%0,%1,%2,%3};"
      : "+f"(c[0]), "+f"(c[1]), "+f"(c[2]), "+f"(c[3])
      : "r"(a[0]), "r"(a[1]), "r"(a[2]), "r"(a[3]), "r"(b0), "r"(b1));
}

// ---------------------------------------------------------------------------
// fp16 tensor-core GEMM: C[M,N] = A[M,K] @ W[N,K]^T (+bias), fp32 out.
// CTA tile 128x256, warp tile 64x64 (8 warps: 2(M) x 4(N)), BK=64.
// SW128-swizzled smem, ldmatrix.x4 frags, cp.async 2-stage pipeline.
// ---------------------------------------------------------------------------
#define HSTAGE 49152                     // 48KB per stage (A 16KB + B 32KB)
#define HGEMM_SMEM (2 * HSTAGE)          // 96KB

__global__ __launch_bounds__(256) void hgemm(
    const __half* __restrict__ A, const __half* __restrict__ Bt,
    float* __restrict__ C, const float* __restrict__ bias, int N, int K) {
  extern __shared__ char smembuf[];
  const uint32_t sbase = smem_u32(smembuf);
  const int tid = threadIdx.x, lane = tid & 31, wid = tid >> 5;
  const int wm = wid & 1, wn = wid >> 1;          // 2 x 4 warp grid
  const size_t bm = (size_t)blockIdx.y * 128;
  const size_t bn = (size_t)blockIdx.x * 256;

  float acc[4][8][4];
#pragma unroll
  for (int mi = 0; mi < 4; ++mi)
#pragma unroll
    for (int nj = 0; nj < 8; ++nj)
#pragma unroll
      for (int j = 0; j < 4; ++j) acc[mi][nj][j] = 0.0f;

  auto issue_loads = [&](int kt, int st) {
    const uint32_t sA = sbase + st * HSTAGE;
    const uint32_t sB = sA + 16384;
    const __half* Ag = A + bm * K + kt * 64;
    const __half* Bg = Bt + bn * K + kt * 64;
#pragma unroll
    for (int i = 0; i < 4; ++i) {                  // A: 128 rows x 8 x 16B
      int idx = tid + i * 256;
      int r = idx >> 3, g = idx & 7;
      cp_async16(sA + r * 128 + ((g ^ (r & 7)) << 4), Ag + (size_t)r * K + g * 8);
    }
#pragma unroll
    for (int i = 0; i < 8; ++i) {                  // B: 256 rows x 8 x 16B
      int idx = tid + i * 256;
      int r = idx >> 3, g = idx & 7;
      cp_async16(sB + r * 128 + ((g ^ (r & 7)) << 4), Bg + (size_t)r * K + g * 8);
    }
    asm volatile("cp.async.commit_group;");
  };

  const int nt = K >> 6;
  issue_loads(0, 0);
  for (int kt = 0; kt < nt; ++kt) {
    const int st = kt & 1;
    if (kt + 1 < nt) {
      issue_loads(kt + 1, st ^ 1);
      asm volatile("cp.async.wait_group 1;");
    } else {
      asm volatile("cp.async.wait_group 0;");
    }
    __syncthreads();
    const uint32_t sA = sbase + st * HSTAGE;
    const uint32_t sB = sA + 16384;
    const int hi8 = (lane >> 4) & 1;
    const int rsel = lane & 15;
#pragma unroll
    for (int ks = 0; ks < 4; ++ks) {
      const int g16 = 2 * ks + hi8;                // 16B granule along K
      uint32_t a[4][4], b[4][4];
#pragma unroll
      for (int mi = 0; mi < 4; ++mi) {
        int mrow = wm * 64 + mi * 16 + rsel;
        ldsm_x4(a[mi], sA + mrow * 128 + ((g16 ^ (mrow & 7)) << 4));
      }
#pragma unroll
      for (int nj = 0; nj < 4; ++nj) {
        int nrow = wn * 64 + nj * 16 + rsel;
        ldsm_x4(b[nj], sB + nrow * 128 + ((g16 ^ (nrow & 7)) << 4));
      }
#pragma unroll
      for (int mi = 0; mi < 4; ++mi)
#pragma unroll
        for (int nj = 0; nj < 8; ++nj)
          mma_f16(acc[mi][nj], a[mi], b[nj >> 1][nj & 1], b[nj >> 1][(nj & 1) + 2]);
    }
    __syncthreads();
  }

  // epilogue: frag c0,c1 -> (row, col..col+1); c2,c3 -> (row+8, ..)
  const int rr = lane >> 2, cc2 = (lane & 3) * 2;
#pragma unroll
  for (int mi = 0; mi < 4; ++mi) {
    size_t row = bm + wm * 64 + mi * 16 + rr;
#pragma unroll
    for (int nj = 0; nj < 8; ++nj) {
      size_t col = bn + wn * 64 + nj * 8 + cc2;
      float b0 = 0.0f, b1 = 0.0f;
      if (bias) { b0 = bias[col]; b1 = bias[col + 1]; }
      *(float2*)(C + row * N + col) =
          make_float2(acc[mi][nj][0] + b0, acc[mi][nj][1] + b1);
      *(float2*)(C + (row + 8) * N + col) =
          make_float2(acc[mi][nj][2] + b0, acc[mi][nj][3] + b1);
    }
  }
}

// ---------------------------------------------------------------------------
// fp32 -> fp16 elementwise convert (8 elems/thread).
// ---------------------------------------------------------------------------
__global__ __launch_bounds__(256) void f2h_kernel(const float* __restrict__ A,
                                                  __half* __restrict__ O) {
  size_t i = ((size_t)blockIdx.x * 256 + threadIdx.x) * 8;
  float4 v0 = *(const float4*)(A + i);
  float4 v1 = *(const float4*)(A + i + 4);
  union { __half2 h[4]; uint4 u; } o;
  o.h[0] = __floats2half2_rn(v0.x, v0.y);
  o.h[1] = __floats2half2_rn(v0.z, v0.w);
  o.h[2] = __floats2half2_rn(v1.x, v1.y);
  o.h[3] = __floats2half2_rn(v1.z, v1.w);
  *(uint4*)(O + i) = o.u;
}

// ---------------------------------------------------------------------------
// fp32 [K,N] -> fp16 [N,K] transpose (32x32 tiles).
// ---------------------------------------------------------------------------
__global__ __launch_bounds__(256) void wtrans_kernel(const float* __restrict__ W,
                                                     __half* __restrict__ O,
                                                     int K, int N) {
  __shared__ float s[32][33];
  const int n0 = blockIdx.x * 32, k0 = blockIdx.y * 32;
  const int tx = threadIdx.x & 31, tg = threadIdx.x >> 5;
#pragma unroll
  for (int j = 0; j < 4; ++j) {
    int kr = tg + j * 8;
    s[kr][tx] = W[(size_t)(k0 + kr) * N + n0 + tx];
  }
  __syncthreads();
#pragma unroll
  for (int j = 0; j < 4; ++j) {
    int nr = tg + j * 8;
    O[(size_t)(n0 + nr) * K + k0 + tx] = __float2half_rn(s[tx][nr]);
  }
}

// ---------------------------------------------------------------------------
// K2: per-batch column sum-of-squares over tokens for q,k columns.
// ---------------------------------------------------------------------------
__global__ __launch_bounds__(256) void sumsq_kernel() {
  const int b = blockIdx.y;
  const int col = blockIdx.x * 64 + (threadIdx.x & 63);
  const int part = threadIdx.x >> 6;
  const float* base = g_Y + (size_t)b * NN * QKV_COLS + col;
  float s = 0.0f;
  for (int n = part; n < NN; n += 4) {
    float v = base[(size_t)n * QKV_COLS];
    s += v * v;
  }
  __shared__ float red[256];
  red[threadIdx.x] = s;
  __syncthreads();
  if (part == 0) {
    int t = threadIdx.x;
    g_sumsq[b * 2048 + col] = red[t] + red[t + 64] + red[t + 128] + red[t + 192];
  }
}

// ---------------------------------------------------------------------------
// K3: partial grams q.k^T per (b,h), 8 token segments.
// ---------------------------------------------------------------------------
__global__ __launch_bounds__(256) void gram_kernel() {
  const int seg = blockIdx.x;
  const int bh = blockIdx.y;
  const int b = bh >> 4, h = bh & 15;
  __shared__ float qs[32][64];
  __shared__ float ks[32][64];
  const int tid = threadIdx.x;
  const int tx = tid & 15, ty = tid >> 4;
  float acc[4][4] = {};

  const float* Yq = g_Y + (size_t)(b * NN + seg * 512) * QKV_COLS + h * DH;
  const float* Yk = Yq + CC;

  for (int ch = 0; ch < 16; ++ch) {
#pragma unroll
    for (int i = 0; i < 2; ++i) {
      int lin = tid + i * 256;
      int r = lin >> 4;
      int c4 = (lin & 15) << 2;
      size_t off = (size_t)(ch * 32 + r) * QKV_COLS + c4;
      *(float4*)&qs[r][c4] = *(const float4*)(Yq + off);
      *(float4*)&ks[r][c4] = *(const float4*)(Yk + off);
    }
    __syncthreads();
#pragma unroll
    for (int r = 0; r < 32; ++r) {
      float4 qa = *(float4*)&qs[r][ty * 4];
      float4 ka = *(float4*)&ks[r][tx * 4];
      float qv[4] = {qa.x, qa.y, qa.z, qa.w};
      float kv[4] = {ka.x, ka.y, ka.z, ka.w};
#pragma unroll
      for (int i = 0; i < 4; ++i)
#pragma unroll
        for (int j = 0; j < 4; ++j)
          acc[i][j] += qv[i] * kv[j];
    }
    __syncthreads();
  }

  float* Sout = g_Spart + (size_t)(bh * 8 + seg) * (DH * DH);
#pragma unroll
  for (int i = 0; i < 4; ++i)
#pragma unroll
    for (int j = 0; j < 4; ++j)
      Sout[(ty * 4 + i) * DH + tx * 4 + j] = acc[i][j];
}

// ---------------------------------------------------------------------------
// K3b: reduce grams, scale by 1/(|q||k|)*temp, softmax over e.
// ---------------------------------------------------------------------------
__global__ __launch_bounds__(256) void softmax_kernel(const float* __restrict__ temp) {
  const int bh = blockIdx.x;
  const int b = bh >> 4, h = bh & 15;
  __shared__ float S[64][65];
  __shared__ float nqv[64], nkv[64];
  const int tid = threadIdx.x;

  if (tid < 64) {
    nqv[tid] = fmaxf(sqrtf(g_sumsq[b * 2048 + h * DH + tid]), 1e-12f);
    nkv[tid] = fmaxf(sqrtf(g_sumsq[b * 2048 + CC + h * DH + tid]), 1e-12f);
  }
  __syncthreads();

  const float tp = temp[h];
  for (int idx = tid; idx < DH * DH; idx += 256) {
    float s = 0.0f;
#pragma unroll
    for (int seg = 0; seg < 8; ++seg)
      s += g_Spart[(size_t)(bh * 8 + seg) * (DH * DH) + idx];
    int d = idx >> 6, e = idx & 63;
    S[d][e] = s / (nqv[d] * nkv[e]) * tp;
  }
  __syncthreads();

  if (tid < 64) {
    int d = tid;
    float m = -3.402823466e38f;
    for (int e = 0; e < 64; ++e) m = fmaxf(m, S[d][e]);
    float sum = 0.0f;
    for (int e = 0; e < 64; ++e) {
      float ex = expf(S[d][e] - m);
      S[d][e] = ex;
      sum += ex;
    }
    float inv = 1.0f / sum;
    float* Ao = g_attn + (size_t)bh * (DH * DH) + d * DH;
    for (int e = 0; e < 64; ++e) Ao[e] = S[d][e] * inv;
  }
}

// ---------------------------------------------------------------------------
// K4: Z = attn @ v in [B,N,C] layout.
// ---------------------------------------------------------------------------
__global__ __launch_bounds__(256) void attnv_kernel() {
  const int bh = blockIdx.y;
  const int b = bh >> 4, h = bh & 15;
  const int n = blockIdx.x * 256 + threadIdx.x;
  __shared__ float As[64][64];
  const int tid = threadIdx.x;

  const float* Ag = g_attn + (size_t)bh * (DH * DH);
#pragma unroll
  for (int i = 0; i < 4; ++i) {
    int lin = tid + i * 256;
    *(float4*)&As[lin >> 4][(lin & 15) << 2] = *(const float4*)(Ag + lin * 4);
  }
  __syncthreads();

  const float* v = g_Y + (size_t)(b * NN + n) * QKV_COLS + 2 * CC + h * DH;
  float z[64];
#pragma unroll
  for (int d = 0; d < 64; ++d) z[d] = 0.0f;

#pragma unroll
  for (int c = 0; c < 4; ++c) {
    float4 v0 = *(const float4*)(v + c * 16 + 0);
    float4 v1 = *(const float4*)(v + c * 16 + 4);
    float4 v2 = *(const float4*)(v + c * 16 + 8);
    float4 v3 = *(const float4*)(v + c * 16 + 12);
#pragma unroll
    for (int d = 0; d < 64; ++d) {
      const float4* Ad = (const float4*)&As[d][c * 16];
      float4 a0 = Ad[0], a1 = Ad[1], a2 = Ad[2], a3 = Ad[3];
      float s = a0.x * v0.x + a0.y * v0.y + a0.z * v0.z + a0.w * v0.w;
      s += a1.x * v1.x + a1.y * v1.y + a1.z * v1.z + a1.w * v1.w;
      s += a2.x * v2.x + a2.y * v2.y + a2.z * v2.z + a2.w * v2.w;
      s += a3.x * v3.x + a3.y * v3.y + a3.z * v3.z + a3.w * v3.w;
      z[d] += s;
    }
  }

  float* zo = g_Z + (size_t)(b * NN + n) * CC + h * DH;
#pragma unroll
  for (int d4 = 0; d4 < 16; ++d4)
    *(float4*)(zo + d4 * 4) =
        make_float4(z[d4 * 4], z[d4 * 4 + 1], z[d4 * 4 + 2], z[d4 * 4 + 3]);
}

// ---------------------------------------------------------------------------
extern "C" void kernel_launch(void* const* d_in, const int* in_sizes, int n_in,
                              void* d_out, int out_size) {
  const float* x      = (const float*)d_in[0];  // [8,4096,1024]
  const float* w_qkv  = (const float*)d_in[1];  // [1024,3072]
  const float* temp   = (const float*)d_in[2];  // [16,1,1]
  const float* w_proj = (const float*)d_in[3];  // [1024,1024]
  const float* b_proj = (const float*)d_in[4];  // [1024]
  float* out = (float*)d_out;                   // [8,4096,1024]

  static float* Y = nullptr;
  static float* Z = nullptr;
  static __half *Ah = nullptr, *Wh = nullptr;
  if (Y == nullptr) {
    cudaGetSymbolAddress((void**)&Y, g_Y);
    cudaGetSymbolAddress((void**)&Z, g_Z);
    cudaGetSymbolAddress((void**)&Ah, g_Af16);
    cudaGetSymbolAddress((void**)&Wh, g_Wf16);
    cudaFuncSetAttribute(hgemm, cudaFuncAttributeMaxDynamicSharedMemorySize,
                         HGEMM_SMEM);
  }

  // prep: x -> fp16, w_qkv -> fp16 [N,K]
  f2h_kernel<<<(size_t)M_ROWS * CC / 2048, 256>>>(x, Ah);
  wtrans_kernel<<<dim3(QKV_COLS / 32, CC / 32), 256>>>(w_qkv, Wh, CC, QKV_COLS);

  // K1: qkv = x @ w_qkv  (fp16 tensor cores, fp32 out)
  hgemm<<<dim3(QKV_COLS / 256, M_ROWS / 128), 256, HGEMM_SMEM>>>(
      Ah, Wh, Y, nullptr, QKV_COLS, CC);

  sumsq_kernel<<<dim3(32, BB), 256>>>();
  gram_kernel<<<dim3(8, BB * HH), 256>>>();
  softmax_kernel<<<BB * HH, 256>>>(temp);
  attnv_kernel<<<dim3(NN / 256, BB * HH), 256>>>();

  // prep: Z -> fp16, w_proj -> fp16 [N,K]
  f2h_kernel<<<(size_t)M_ROWS * CC / 2048, 256>>>(Z, Ah);
  wtrans_kernel<<<dim3(CC / 32, CC / 32), 256>>>(w_proj, Wh, CC, CC);

  // K5: out = Z @ w_proj + b_proj
  hgemm<<<dim3(CC / 256, M_ROWS / 128), 256, HGEMM_SMEM>>>(
      Ah, Wh, out, b_proj, CC, CC);
}

// round 7
// speedup vs baseline: 5.5646x; 1.0654x over previous
#include <cuda_runtime.h>
#include <cuda_fp16.h>
#include <math.h>
#include <stdint.h>

// Problem constants: B=8, N=4096, C=1024, H=16, dh=64
#define BB 8
#define NN 4096
#define CC 1024
#define HH 16
#define DH 64
#define M_ROWS (BB * NN)          // 32768
#define QKV_COLS (3 * CC)         // 3072

// ---------------- static scratch (no runtime allocation allowed) -------------
__device__ __align__(128) __half g_Yh[(size_t)M_ROWS * QKV_COLS];  // qkv fp16
__device__ __align__(128) __half g_Zh[(size_t)M_ROWS * CC];        // attn@v fp16
__device__ __align__(128) float g_Spart[(size_t)BB * HH * 8 * DH * DH];
__device__ __align__(128) float g_attn[(size_t)BB * HH * DH * DH];
__device__ __align__(128) float g_sumsq[BB * 2 * CC];
__device__ __align__(128) __half g_Af16[(size_t)M_ROWS * CC];      // x fp16 [M,K]
__device__ __align__(128) __half g_Wf16[(size_t)QKV_COLS * CC];    // W^T fp16 [N,K]

// ============================ helpers =======================================
__device__ __forceinline__ uint32_t smem_u32(const void* p) {
  uint32_t a;
  asm("{ .reg .u64 t; cvta.to.shared.u64 t, %1; cvt.u32.u64 %0, t; }" : "=r"(a) : "l"(p));
  return a;
}
__device__ __forceinline__ void cp_async16(uint32_t dst, const void* src) {
  asm volatile("cp.async.cg.shared.global [%0], [%1], 16;" :: "r"(dst), "l"(src));
}
__device__ __forceinline__ void ldsm_x4(uint32_t* r, uint32_t addr) {
  asm volatile("ldmatrix.sync.aligned.m8n8.x4.shared.b16 {%0,%1,%2,%3}, [%4];"
               : "=r"(r[0]), "=r"(r[1]), "=r"(r[2]), "=r"(r[3]) : "r"(addr));
}
__device__ __forceinline__ void mma_f16(float* c, const uint32_t* a, uint32_t b0,
                                        uint32_t b1) {
  asm volatile(
      "mma.sync.aligned.m16n8k16.row.col.f32.f16.f16.f32 "
      "{%0,%1,%2,%3}, {%4,%5,%6,%7}, {%8,%9}, {%0,%1,%2,%3};"
      : "+f"(c[0]), "+f"(c[1]), "+f"(c[2]), "+f"(c[3])
      : "r"(a[0]), "r"(a[1]), "r"(a[2]), "r"(a[3]), "r"(b0), "r"(b1));
}

// ---------------------------------------------------------------------------
// fp16 tensor-core GEMM: C[M,N] = A[M,K] @ W[N,K]^T, CTA tile 128x256,
// warp tile 64x64 (8 warps), BK=64. 3-stage cp.async pipeline, one
// __syncthreads per k-tile. OUT_HALF: fp16 out; else fp32 (+bias).
// ---------------------------------------------------------------------------
#define HSTAGE 49152                     // A 16KB + B 32KB
#define HGEMM_SMEM (3 * HSTAGE)          // 144KB

template <int OUT_HALF>
__global__ __launch_bounds__(256) void hgemm(
    const __half* __restrict__ A, const __half* __restrict__ Bt,
    void* __restrict__ Cv, const float* __restrict__ bias, int N, int K) {
  extern __shared__ char smembuf[];
  const uint32_t sbase = smem_u32(smembuf);
  const int tid = threadIdx.x, lane = tid & 31, wid = tid >> 5;
  const int wm = wid & 1, wn = wid >> 1;          // 2 x 4 warp grid
  const size_t bm = (size_t)blockIdx.y * 128;
  const size_t bn = (size_t)blockIdx.x * 256;

  float acc[4][8][4];
#pragma unroll
  for (int mi = 0; mi < 4; ++mi)
#pragma unroll
    for (int nj = 0; nj < 8; ++nj)
#pragma unroll
      for (int j = 0; j < 4; ++j) acc[mi][nj][j] = 0.0f;

  auto issue_loads = [&](int kt, int st) {
    const uint32_t sA = sbase + st * HSTAGE;
    const uint32_t sB = sA + 16384;
    const __half* Ag = A + bm * K + kt * 64;
    const __half* Bg = Bt + bn * K + kt * 64;
#pragma unroll
    for (int i = 0; i < 4; ++i) {                  // A: 128 rows x 8 x 16B
      int idx = tid + i * 256;
      int r = idx >> 3, g = idx & 7;
      cp_async16(sA + r * 128 + ((g ^ (r & 7)) << 4), Ag + (size_t)r * K + g * 8);
    }
#pragma unroll
    for (int i = 0; i < 8; ++i) {                  // B: 256 rows x 8 x 16B
      int idx = tid + i * 256;
      int r = idx >> 3, g = idx & 7;
      cp_async16(sB + r * 128 + ((g ^ (r & 7)) << 4), Bg + (size_t)r * K + g * 8);
    }
    asm volatile("cp.async.commit_group;");
  };

  const int nt = K >> 6;
  issue_loads(0, 0);
  if (nt > 1) issue_loads(1, 1);

  const int hi8 = (lane >> 4) & 1;
  const int rsel = lane & 15;

  for (int kt = 0; kt < nt; ++kt) {
    if (kt + 1 < nt) {
      asm volatile("cp.async.wait_group 1;");
    } else {
      asm volatile("cp.async.wait_group 0;");
    }
    __syncthreads();
    if (kt + 2 < nt) issue_loads(kt + 2, (kt + 2) % 3);

    const int st = kt % 3;
    const uint32_t sA = sbase + st * HSTAGE;
    const uint32_t sB = sA + 16384;
#pragma unroll
    for (int ks = 0; ks < 4; ++ks) {
      const int g16 = 2 * ks + hi8;
      uint32_t a[4][4], b[4][4];
#pragma unroll
      for (int mi = 0; mi < 4; ++mi) {
        int mrow = wm * 64 + mi * 16 + rsel;
        ldsm_x4(a[mi], sA + mrow * 128 + ((g16 ^ (mrow & 7)) << 4));
      }
#pragma unroll
      for (int nj = 0; nj < 4; ++nj) {
        int nrow = wn * 64 + nj * 16 + rsel;
        ldsm_x4(b[nj], sB + nrow * 128 + ((g16 ^ (nrow & 7)) << 4));
      }
#pragma unroll
      for (int mi = 0; mi < 4; ++mi)
#pragma unroll
        for (int nj = 0; nj < 8; ++nj)
          mma_f16(acc[mi][nj], a[mi], b[nj >> 1][nj & 1], b[nj >> 1][(nj & 1) + 2]);
    }
  }

  // epilogue
  const int rr = lane >> 2, cc2 = (lane & 3) * 2;
#pragma unroll
  for (int mi = 0; mi < 4; ++mi) {
    size_t row = bm + wm * 64 + mi * 16 + rr;
#pragma unroll
    for (int nj = 0; nj < 8; ++nj) {
      size_t col = bn + wn * 64 + nj * 8 + cc2;
      if (OUT_HALF) {
        __half* C = (__half*)Cv;
        *(__half2*)(C + row * N + col) =
            __floats2half2_rn(acc[mi][nj][0], acc[mi][nj][1]);
        *(__half2*)(C + (row + 8) * N + col) =
            __floats2half2_rn(acc[mi][nj][2], acc[mi][nj][3]);
      } else {
        float* C = (float*)Cv;
        float b0 = 0.0f, b1 = 0.0f;
        if (bias) { b0 = bias[col]; b1 = bias[col + 1]; }
        *(float2*)(C + row * N + col) =
            make_float2(acc[mi][nj][0] + b0, acc[mi][nj][1] + b1);
        *(float2*)(C + (row + 8) * N + col) =
            make_float2(acc[mi][nj][2] + b0, acc[mi][nj][3] + b1);
      }
    }
  }
}

// ---------------------------------------------------------------------------
// fp32 -> fp16 elementwise convert (8 elems/thread).
// ---------------------------------------------------------------------------
__global__ __launch_bounds__(256) void f2h_kernel(const float* __restrict__ A,
                                                  __half* __restrict__ O) {
  size_t i = ((size_t)blockIdx.x * 256 + threadIdx.x) * 8;
  float4 v0 = *(const float4*)(A + i);
  float4 v1 = *(const float4*)(A + i + 4);
  union { __half2 h[4]; uint4 u; } o;
  o.h[0] = __floats2half2_rn(v0.x, v0.y);
  o.h[1] = __floats2half2_rn(v0.z, v0.w);
  o.h[2] = __floats2half2_rn(v1.x, v1.y);
  o.h[3] = __floats2half2_rn(v1.z, v1.w);
  *(uint4*)(O + i) = o.u;
}

// ---------------------------------------------------------------------------
// fp32 [K,N] -> fp16 [N,K] transpose (32x32 tiles).
// ---------------------------------------------------------------------------
__global__ __launch_bounds__(256) void wtrans_kernel(const float* __restrict__ W,
                                                     __half* __restrict__ O,
                                                     int K, int N) {
  __shared__ float s[32][33];
  const int n0 = blockIdx.x * 32, k0 = blockIdx.y * 32;
  const int tx = threadIdx.x & 31, tg = threadIdx.x >> 5;
#pragma unroll
  for (int j = 0; j < 4; ++j) {
    int kr = tg + j * 8;
    s[kr][tx] = W[(size_t)(k0 + kr) * N + n0 + tx];
  }
  __syncthreads();
#pragma unroll
  for (int j = 0; j < 4; ++j) {
    int nr = tg + j * 8;
    O[(size_t)(n0 + nr) * K + k0 + tx] = __float2half_rn(s[tx][nr]);
  }
}

// ---------------------------------------------------------------------------
// K2: per-batch column sum-of-squares over tokens for q,k columns (fp16 in).
// ---------------------------------------------------------------------------
__global__ __launch_bounds__(256) void sumsq_kernel() {
  const int b = blockIdx.y;
  const int col = blockIdx.x * 64 + (threadIdx.x & 63);
  const int part = threadIdx.x >> 6;
  const __half* base = g_Yh + (size_t)b * NN * QKV_COLS + col;
  float s = 0.0f;
  for (int n = part; n < NN; n += 4) {
    float v = __half2float(base[(size_t)n * QKV_COLS]);
    s += v * v;
  }
  __shared__ float red[256];
  red[threadIdx.x] = s;
  __syncthreads();
  if (part == 0) {
    int t = threadIdx.x;
    g_sumsq[b * 2048 + col] = red[t] + red[t + 64] + red[t + 128] + red[t + 192];
  }
}

// ---------------------------------------------------------------------------
// K3: partial grams q.k^T per (b,h), 8 token segments (fp16 in, fp32 math).
// ---------------------------------------------------------------------------
__global__ __launch_bounds__(256) void gram_kernel() {
  const int seg = blockIdx.x;
  const int bh = blockIdx.y;
  const int b = bh >> 4, h = bh & 15;
  __shared__ float qs[32][64];
  __shared__ float ks[32][64];
  const int tid = threadIdx.x;
  const int tx = tid & 15, ty = tid >> 4;
  float acc[4][4] = {};

  const __half* Yq = g_Yh + (size_t)(b * NN + seg * 512) * QKV_COLS + h * DH;
  const __half* Yk = Yq + CC;

  const int r = tid >> 3;              // 0..31
  const int c8 = (tid & 7) << 3;       // 0..56
  for (int ch = 0; ch < 16; ++ch) {
    size_t off = (size_t)(ch * 32 + r) * QKV_COLS + c8;
    union { uint4 u; __half2 h[4]; } vq, vk;
    vq.u = *(const uint4*)(Yq + off);
    vk.u = *(const uint4*)(Yk + off);
#pragma unroll
    for (int j = 0; j < 4; ++j) {
      float2 fq = __half22float2(vq.h[j]);
      float2 fk = __half22float2(vk.h[j]);
      qs[r][c8 + 2 * j] = fq.x; qs[r][c8 + 2 * j + 1] = fq.y;
      ks[r][c8 + 2 * j] = fk.x; ks[r][c8 + 2 * j + 1] = fk.y;
    }
    __syncthreads();
#pragma unroll
    for (int rr = 0; rr < 32; ++rr) {
      float4 qa = *(float4*)&qs[rr][ty * 4];
      float4 ka = *(float4*)&ks[rr][tx * 4];
      float qv[4] = {qa.x, qa.y, qa.z, qa.w};
      float kv[4] = {ka.x, ka.y, ka.z, ka.w};
#pragma unroll
      for (int i = 0; i < 4; ++i)
#pragma unroll
        for (int j = 0; j < 4; ++j)
          acc[i][j] += qv[i] * kv[j];
    }
    __syncthreads();
  }

  float* Sout = g_Spart + (size_t)(bh * 8 + seg) * (DH * DH);
#pragma unroll
  for (int i = 0; i < 4; ++i)
#pragma unroll
    for (int j = 0; j < 4; ++j)
      Sout[(ty * 4 + i) * DH + tx * 4 + j] = acc[i][j];
}

// ---------------------------------------------------------------------------
// K3b: reduce grams, scale by 1/(|q||k|)*temp, softmax over e.
// ---------------------------------------------------------------------------
__global__ __launch_bounds__(256) void softmax_kernel(const float* __restrict__ temp) {
  const int bh = blockIdx.x;
  const int b = bh >> 4, h = bh & 15;
  __shared__ float S[64][65];
  __shared__ float nqv[64], nkv[64];
  const int tid = threadIdx.x;

  if (tid < 64) {
    nqv[tid] = fmaxf(sqrtf(g_sumsq[b * 2048 + h * DH + tid]), 1e-12f);
    nkv[tid] = fmaxf(sqrtf(g_sumsq[b * 2048 + CC + h * DH + tid]), 1e-12f);
  }
  __syncthreads();

  const float tp = temp[h];
  for (int idx = tid; idx < DH * DH; idx += 256) {
    float s = 0.0f;
#pragma unroll
    for (int seg = 0; seg < 8; ++seg)
      s += g_Spart[(size_t)(bh * 8 + seg) * (DH * DH) + idx];
    int d = idx >> 6, e = idx & 63;
    S[d][e] = s / (nqv[d] * nkv[e]) * tp;
  }
  __syncthreads();

  if (tid < 64) {
    int d = tid;
    float m = -3.402823466e38f;
    for (int e = 0; e < 64; ++e) m = fmaxf(m, S[d][e]);
    float sum = 0.0f;
    for (int e = 0; e < 64; ++e) {
      float ex = expf(S[d][e] - m);
      S[d][e] = ex;
      sum += ex;
    }
    float inv = 1.0f / sum;
    float* Ao = g_attn + (size_t)bh * (DH * DH) + d * DH;
    for (int e = 0; e < 64; ++e) Ao[e] = S[d][e] * inv;
  }
}

// ---------------------------------------------------------------------------
// K4: Z = attn @ v (v fp16), writes Z fp16 in [B,N,C] layout.
// ---------------------------------------------------------------------------
__global__ __launch_bounds__(256) void attnv_kernel() {
  const int bh = blockIdx.y;
  const int b = bh >> 4, h = bh & 15;
  const int n = blockIdx.x * 256 + threadIdx.x;
  __shared__ float As[64][64];
  const int tid = threadIdx.x;

  const float* Ag = g_attn + (size_t)bh * (DH * DH);
#pragma unroll
  for (int i = 0; i < 4; ++i) {
    int lin = tid + i * 256;
    *(float4*)&As[lin >> 4][(lin & 15) << 2] = *(const float4*)(Ag + lin * 4);
  }
  __syncthreads();

  const __half* v = g_Yh + (size_t)(b * NN + n) * QKV_COLS + 2 * CC + h * DH;
  float z[64];
#pragma unroll
  for (int d = 0; d < 64; ++d) z[d] = 0.0f;

#pragma unroll
  for (int c = 0; c < 4; ++c) {            // chunks of 16 e-values
    union { uint4 u; __half2 h[4]; } p0, p1;
    p0.u = *(const uint4*)(v + c * 16);
    p1.u = *(const uint4*)(v + c * 16 + 8);
    float vf[16];
#pragma unroll
    for (int j = 0; j < 4; ++j) {
      float2 f0 = __half22float2(p0.h[j]);
      float2 f1 = __half22float2(p1.h[j]);
      vf[2 * j] = f0.x; vf[2 * j + 1] = f0.y;
      vf[8 + 2 * j] = f1.x; vf[8 + 2 * j + 1] = f1.y;
    }
#pragma unroll
    for (int d = 0; d < 64; ++d) {
      const float* Ad = &As[d][c * 16];
      float s = 0.0f;
#pragma unroll
      for (int j = 0; j < 16; ++j) s += Ad[j] * vf[j];
      z[d] += s;
    }
  }

  __half* zo = g_Zh + (size_t)(b * NN + n) * CC + h * DH;
#pragma unroll
  for (int d8 = 0; d8 < 8; ++d8) {
    union { uint4 u; __half2 h[4]; } o;
#pragma unroll
    for (int j = 0; j < 4; ++j)
      o.h[j] = __floats2half2_rn(z[d8 * 8 + 2 * j], z[d8 * 8 + 2 * j + 1]);
    *(uint4*)(zo + d8 * 8) = o.u;
  }
}

// ---------------------------------------------------------------------------
extern "C" void kernel_launch(void* const* d_in, const int* in_sizes, int n_in,
                              void* d_out, int out_size) {
  const float* x      = (const float*)d_in[0];  // [8,4096,1024]
  const float* w_qkv  = (const float*)d_in[1];  // [1024,3072]
  const float* temp   = (const float*)d_in[2];  // [16,1,1]
  const float* w_proj = (const float*)d_in[3];  // [1024,1024]
  const float* b_proj = (const float*)d_in[4];  // [1024]
  float* out = (float*)d_out;                   // [8,4096,1024]

  static __half *Yh = nullptr, *Zh = nullptr, *Ah = nullptr, *Wh = nullptr;
  if (Yh == nullptr) {
    cudaGetSymbolAddress((void**)&Yh, g_Yh);
    cudaGetSymbolAddress((void**)&Zh, g_Zh);
    cudaGetSymbolAddress((void**)&Ah, g_Af16);
    cudaGetSymbolAddress((void**)&Wh, g_Wf16);
    cudaFuncSetAttribute(hgemm<0>, cudaFuncAttributeMaxDynamicSharedMemorySize,
                         HGEMM_SMEM);
    cudaFuncSetAttribute(hgemm<1>, cudaFuncAttributeMaxDynamicSharedMemorySize,
                         HGEMM_SMEM);
  }

  // prep: x -> fp16, w_qkv -> fp16 [N,K]
  f2h_kernel<<<(size_t)M_ROWS * CC / 2048, 256>>>(x, Ah);
  wtrans_kernel<<<dim3(QKV_COLS / 32, CC / 32), 256>>>(w_qkv, Wh, CC, QKV_COLS);

  // K1: qkv = x @ w_qkv -> fp16 Yh
  hgemm<1><<<dim3(QKV_COLS / 256, M_ROWS / 128), 256, HGEMM_SMEM>>>(
      Ah, Wh, Yh, nullptr, QKV_COLS, CC);

  sumsq_kernel<<<dim3(32, BB), 256>>>();
  gram_kernel<<<dim3(8, BB * HH), 256>>>();
  softmax_kernel<<<BB * HH, 256>>>(temp);
  attnv_kernel<<<dim3(NN / 256, BB * HH), 256>>>();   // writes Zh fp16

  // prep: w_proj -> fp16 [N,K]
  wtrans_kernel<<<dim3(CC / 32, CC / 32), 256>>>(w_proj, Wh, CC, CC);

  // K5: out = Z @ w_proj + b_proj (fp32 out)
  hgemm<0><<<dim3(CC / 256, M_ROWS / 128), 256, HGEMM_SMEM>>>(
      Zh, Wh, out, b_proj, CC, CC);
}

// round 9
// speedup vs baseline: 6.8175x; 1.2252x over previous
#include <cuda_runtime.h>
#include <cuda_fp16.h>
#include <math.h>
#include <stdint.h>

// Problem constants: B=8, N=4096, C=1024, H=16, dh=64
#define BB 8
#define NN 4096
#define CC 1024
#define HH 16
#define DH 64
#define M_ROWS (BB * NN)          // 32768
#define QKV_COLS (3 * CC)         // 3072

// ---------------- static scratch -------------------------------------------
__device__ __align__(128) __half g_Yh[(size_t)M_ROWS * QKV_COLS];  // qkv fp16
__device__ __align__(128) __half g_Zh[(size_t)M_ROWS * CC];        // attn@v fp16
__device__ __align__(128) __half g_attnh[(size_t)BB * HH * DH * DH]; // attn fp16 [bh][d][e]
__device__ __align__(128) float g_sumsq[BB * 2 * CC];
__device__ __align__(128) float g_sspart[(size_t)(M_ROWS / 128) * 2048]; // per-Mtile col sumsq
__device__ __align__(128) __half g_Af16[(size_t)M_ROWS * CC];      // x fp16 [M,K]
__device__ __align__(128) __half g_Wf16[(size_t)QKV_COLS * CC];    // W^T fp16 [N,K]

// ============================ helpers =======================================
__device__ __forceinline__ uint32_t smem_u32(const void* p) {
  uint32_t a;
  asm("{ .reg .u64 t; cvta.to.shared.u64 t, %1; cvt.u32.u64 %0, t; }" : "=r"(a) : "l"(p));
  return a;
}
__device__ __forceinline__ void cp_async16(uint32_t dst, const void* src) {
  asm volatile("cp.async.cg.shared.global [%0], [%1], 16;" :: "r"(dst), "l"(src));
}
__device__ __forceinline__ void ldsm_x4(uint32_t* r, uint32_t addr) {
  asm volatile("ldmatrix.sync.aligned.m8n8.x4.shared.b16 {%0,%1,%2,%3}, [%4];"
               : "=r"(r[0]), "=r"(r[1]), "=r"(r[2]), "=r"(r[3]) : "r"(addr));
}
__device__ __forceinline__ void ldsm_x4_t(uint32_t* r, uint32_t addr) {
  asm volatile("ldmatrix.sync.aligned.m8n8.x4.trans.shared.b16 {%0,%1,%2,%3}, [%4];"
               : "=r"(r[0]), "=r"(r[1]), "=r"(r[2]), "=r"(r[3]) : "r"(addr));
}
__device__ __forceinline__ void ldsm_x2(uint32_t* r, uint32_t addr) {
  asm volatile("ldmatrix.sync.aligned.m8n8.x2.shared.b16 {%0,%1}, [%2];"
               : "=r"(r[0]), "=r"(r[1]) : "r"(addr));
}
__device__ __forceinline__ void ldsm_x2_t(uint32_t* r, uint32_t addr) {
  asm volatile("ldmatrix.sync.aligned.m8n8.x2.trans.shared.b16 {%0,%1}, [%2];"
               : "=r"(r[0]), "=r"(r[1]) : "r"(addr));
}
__device__ __forceinline__ void mma_f16(float* c, const uint32_t* a, uint32_t b0,
                                        uint32_t b1) {
  asm volatile(
      "mma.sync.aligned.m16n8k16.row.col.f32.f16.f16.f32 "
      "{%0,%1,%2,%3}, {%4,%5,%6,%7}, {%8,%9}, {%0,%1,%2,%3};"
      : "+f"(c[0]), "+f"(c[1]), "+f"(c[2]), "+f"(c[3])
      : "r"(a[0]), "r"(a[1]), "r"(a[2]), "r"(a[3]), "r"(b0), "r"(b1));
}

// ---------------------------------------------------------------------------
// fp16 tensor-core GEMM: C[M,N] = A[M,K] @ W[N,K]^T, CTA tile 128x256,
// warp tile 64x64 (8 warps), BK=64, 3-stage cp.async pipeline.
// OUT_HALF: fp16 out. SUMSQ: emit per-(Mtile,col) sum-of-squares partials
// for cols < 2048 (q,k) -- deterministic fixed-order smem reduction.
// ---------------------------------------------------------------------------
#define HSTAGE 49152
#define HGEMM_SMEM (3 * HSTAGE)          // 144KB

template <int OUT_HALF, int SUMSQ>
__global__ __launch_bounds__(256) void hgemm(
    const __half* __restrict__ A, const __half* __restrict__ Bt,
    void* __restrict__ Cv, const float* __restrict__ bias, int N, int K) {
  extern __shared__ char smembuf[];
  const uint32_t sbase = smem_u32(smembuf);
  const int tid = threadIdx.x, lane = tid & 31, wid = tid >> 5;
  const int wm = wid & 1, wn = wid >> 1;
  const size_t bm = (size_t)blockIdx.y * 128;
  const size_t bn = (size_t)blockIdx.x * 256;

  float acc[4][8][4];
#pragma unroll
  for (int mi = 0; mi < 4; ++mi)
#pragma unroll
    for (int nj = 0; nj < 8; ++nj)
#pragma unroll
      for (int j = 0; j < 4; ++j) acc[mi][nj][j] = 0.0f;

  auto issue_loads = [&](int kt, int st) {
    const uint32_t sA = sbase + st * HSTAGE;
    const uint32_t sB = sA + 16384;
    const __half* Ag = A + bm * K + kt * 64;
    const __half* Bg = Bt + bn * K + kt * 64;
#pragma unroll
    for (int i = 0; i < 4; ++i) {
      int idx = tid + i * 256;
      int r = idx >> 3, g = idx & 7;
      cp_async16(sA + r * 128 + ((g ^ (r & 7)) << 4), Ag + (size_t)r * K + g * 8);
    }
#pragma unroll
    for (int i = 0; i < 8; ++i) {
      int idx = tid + i * 256;
      int r = idx >> 3, g = idx & 7;
      cp_async16(sB + r * 128 + ((g ^ (r & 7)) << 4), Bg + (size_t)r * K + g * 8);
    }
    asm volatile("cp.async.commit_group;");
  };

  const int nt = K >> 6;
  issue_loads(0, 0);
  if (nt > 1) issue_loads(1, 1);

  const int hi8 = (lane >> 4) & 1;
  const int rsel = lane & 15;

  for (int kt = 0; kt < nt; ++kt) {
    if (kt + 1 < nt) {
      asm volatile("cp.async.wait_group 1;");
    } else {
      asm volatile("cp.async.wait_group 0;");
    }
    __syncthreads();
    if (kt + 2 < nt) issue_loads(kt + 2, (kt + 2) % 3);

    const int st = kt % 3;
    const uint32_t sA = sbase + st * HSTAGE;
    const uint32_t sB = sA + 16384;
#pragma unroll
    for (int ks = 0; ks < 4; ++ks) {
      const int g16 = 2 * ks + hi8;
      uint32_t a[4][4], b[4][4];
#pragma unroll
      for (int mi = 0; mi < 4; ++mi) {
        int mrow = wm * 64 + mi * 16 + rsel;
        ldsm_x4(a[mi], sA + mrow * 128 + ((g16 ^ (mrow & 7)) << 4));
      }
#pragma unroll
      for (int nj = 0; nj < 4; ++nj) {
        int nrow = wn * 64 + nj * 16 + rsel;
        ldsm_x4(b[nj], sB + nrow * 128 + ((g16 ^ (nrow & 7)) << 4));
      }
#pragma unroll
      for (int mi = 0; mi < 4; ++mi)
#pragma unroll
        for (int nj = 0; nj < 8; ++nj)
          mma_f16(acc[mi][nj], a[mi], b[nj >> 1][nj & 1], b[nj >> 1][(nj & 1) + 2]);
    }
  }

  const int rr = lane >> 2, cc2 = (lane & 3) * 2;
#pragma unroll
  for (int mi = 0; mi < 4; ++mi) {
    size_t row = bm + wm * 64 + mi * 16 + rr;
#pragma unroll
    for (int nj = 0; nj < 8; ++nj) {
      size_t col = bn + wn * 64 + nj * 8 + cc2;
      if (OUT_HALF) {
        __half* C = (__half*)Cv;
        *(__half2*)(C + row * N + col) =
            __floats2half2_rn(acc[mi][nj][0], acc[mi][nj][1]);
        *(__half2*)(C + (row + 8) * N + col) =
            __floats2half2_rn(acc[mi][nj][2], acc[mi][nj][3]);
      } else {
        float* C = (float*)Cv;
        float b0 = 0.0f, b1 = 0.0f;
        if (bias) { b0 = bias[col]; b1 = bias[col + 1]; }
        *(float2*)(C + row * N + col) =
            make_float2(acc[mi][nj][0] + b0, acc[mi][nj][1] + b1);
        *(float2*)(C + (row + 8) * N + col) =
            make_float2(acc[mi][nj][2] + b0, acc[mi][nj][3] + b1);
      }
    }
  }

  if (SUMSQ) {
    if (bn < 2048) {
      __syncthreads();                      // pipeline smem now dead
      float* sq = (float*)smembuf;          // [256 cols][16 slots]
      const int slot = wm * 8 + rr;
#pragma unroll
      for (int nj = 0; nj < 8; ++nj) {
        int c0 = wn * 64 + nj * 8 + cc2;
        float p0 = 0.0f, p1 = 0.0f;
#pragma unroll
        for (int mi = 0; mi < 4; ++mi) {
          p0 += acc[mi][nj][0] * acc[mi][nj][0] + acc[mi][nj][2] * acc[mi][nj][2];
          p1 += acc[mi][nj][1] * acc[mi][nj][1] + acc[mi][nj][3] * acc[mi][nj][3];
        }
        sq[c0 * 16 + slot] = p0;
        sq[(c0 + 1) * 16 + slot] = p1;
      }
      __syncthreads();
      float s = 0.0f;
#pragma unroll
      for (int j = 0; j < 16; ++j) s += sq[tid * 16 + j];
      g_sspart[(size_t)blockIdx.y * 2048 + bn + tid] = s;
    }
  }
}

// ---------------------------------------------------------------------------
// Reduce per-Mtile sumsq partials -> g_sumsq[b*2048 + col]. Deterministic.
// ---------------------------------------------------------------------------
__global__ __launch_bounds__(256) void sumsq_reduce() {
  const int c = blockIdx.x * 256 + threadIdx.x;   // 0..2047
  const int b = blockIdx.y;
  float s = 0.0f;
#pragma unroll
  for (int t = 0; t < 32; ++t)
    s += g_sspart[(size_t)(b * 32 + t) * 2048 + c];
  g_sumsq[b * 2048 + c] = s;
}

// ---------------------------------------------------------------------------
// fp32 -> fp16 elementwise convert.
// ---------------------------------------------------------------------------
__global__ __launch_bounds__(256) void f2h_kernel(const float* __restrict__ A,
                                                  __half* __restrict__ O) {
  size_t i = ((size_t)blockIdx.x * 256 + threadIdx.x) * 8;
  float4 v0 = *(const float4*)(A + i);
  float4 v1 = *(const float4*)(A + i + 4);
  union { __half2 h[4]; uint4 u; } o;
  o.h[0] = __floats2half2_rn(v0.x, v0.y);
  o.h[1] = __floats2half2_rn(v0.z, v0.w);
  o.h[2] = __floats2half2_rn(v1.x, v1.y);
  o.h[3] = __floats2half2_rn(v1.z, v1.w);
  *(uint4*)(O + i) = o.u;
}

// ---------------------------------------------------------------------------
// fp32 [K,N] -> fp16 [N,K] transpose (32x32 tiles).
// ---------------------------------------------------------------------------
__global__ __launch_bounds__(256) void wtrans_kernel(const float* __restrict__ W,
                                                     __half* __restrict__ O,
                                                     int K, int N) {
  __shared__ float s[32][33];
  const int n0 = blockIdx.x * 32, k0 = blockIdx.y * 32;
  const int tx = threadIdx.x & 31, tg = threadIdx.x >> 5;
#pragma unroll
  for (int j = 0; j < 4; ++j) {
    int kr = tg + j * 8;
    s[kr][tx] = W[(size_t)(k0 + kr) * N + n0 + tx];
  }
  __syncthreads();
#pragma unroll
  for (int j = 0; j < 4; ++j) {
    int nr = tg + j * 8;
    O[(size_t)(n0 + nr) * K + k0 + tx] = __float2half_rn(s[tx][nr]);
  }
}

// ---------------------------------------------------------------------------
// Fused gram + softmax per (b,h). Tensor-core gram S = q k^T over 4096
// tokens (k-dim), warp w owns e-slice [w*8, w*8+8). Then in-CTA softmax with
// folded 1/(|q||k|)*temp; writes attn fp16 [d][e].
// q[d][n] lives at Yh[n][h*64+d] -> ldmatrix.trans. Swizzled smem tiles.
// ---------------------------------------------------------------------------
#define GRSM_SMEM 32768   // qt 16KB + kt 16KB; S (fp32 64x68) overlays after

__global__ __launch_bounds__(256) void gramsm_kernel(const float* __restrict__ temp) {
  extern __shared__ char gsm[];
  __shared__ float nq[64], nk[64];
  const uint32_t qb = smem_u32(gsm);
  const uint32_t kb = qb + 16384;
  const int bh = blockIdx.x, b = bh >> 4, h = bh & 15;
  const int tid = threadIdx.x, lane = tid & 31, wid = tid >> 5;
  const __half* Yq = g_Yh + (size_t)b * NN * QKV_COLS + h * DH;
  const __half* Yk = Yq + CC;

  float acc[4][4] = {};        // mi (d 16-blocks) x frag
  const int e0 = wid * 8;      // warp's e-slice; e-granule == wid

  for (int ch = 0; ch < 32; ++ch) {        // 32 chunks of 128 tokens
    __syncthreads();
#pragma unroll
    for (int i = 0; i < 4; ++i) {          // 1024 granules per tile
      int idx = tid + i * 256;
      int r = idx >> 3, g = idx & 7;
      size_t go = (size_t)(ch * 128 + r) * QKV_COLS + g * 8;
      uint32_t so = r * 128 + ((g ^ (r & 7)) << 4);
      cp_async16(qb + so, Yq + go);
      cp_async16(kb + so, Yk + go);
    }
    asm volatile("cp.async.commit_group;");
    asm volatile("cp.async.wait_group 0;");
    __syncthreads();
#pragma unroll
    for (int s = 0; s < 8; ++s) {          // 8 k16 steps
      const int tokA = s * 16 + (lane & 7) + ((lane >> 4) << 3);
      uint32_t a[4][4];
#pragma unroll
      for (int mi = 0; mi < 4; ++mi) {
        int gd = mi * 2 + ((lane >> 3) & 1);
        ldsm_x4_t(a[mi], qb + tokA * 128 + ((gd ^ (tokA & 7)) << 4));
      }
      const int tokB = s * 16 + (lane & 7) + (((lane >> 3) & 1) << 3);
      uint32_t bf[2];
      ldsm_x2_t(bf, kb + tokB * 128 + ((wid ^ (tokB & 7)) << 4));
#pragma unroll
      for (int mi = 0; mi < 4; ++mi)
        mma_f16(acc[mi], a[mi], bf[0], bf[1]);
    }
  }
  __syncthreads();             // qt/kt dead; S overlays

  if (tid < 64) {
    nq[tid] = fmaxf(sqrtf(g_sumsq[b * 2048 + h * DH + tid]), 1e-12f);
    nk[tid] = fmaxf(sqrtf(g_sumsq[b * 2048 + CC + h * DH + tid]), 1e-12f);
  }

  float* S = (float*)gsm;      // [64][68]
  const int rr = lane >> 2, cc2 = (lane & 3) * 2;
#pragma unroll
  for (int mi = 0; mi < 4; ++mi) {
    S[(mi * 16 + rr) * 68 + e0 + cc2]     = acc[mi][0];
    S[(mi * 16 + rr) * 68 + e0 + cc2 + 1] = acc[mi][1];
    S[(mi * 16 + 8 + rr) * 68 + e0 + cc2]     = acc[mi][2];
    S[(mi * 16 + 8 + rr) * 68 + e0 + cc2 + 1] = acc[mi][3];
  }
  __syncthreads();

  if (tid < 64) {
    const int d = tid;
    const float sc = temp[h] / nq[d];
    float row[64];
    float m = -3.402823466e38f;
#pragma unroll
    for (int e = 0; e < 64; ++e) {
      row[e] = S[d * 68 + e] * sc / nk[e];
      m = fmaxf(m, row[e]);
    }
    float sum = 0.0f;
#pragma unroll
    for (int e = 0; e < 64; ++e) {
      row[e] = expf(row[e] - m);
      sum += row[e];
    }
    const float inv = 1.0f / sum;
    __half2* Ao = (__half2*)(g_attnh + (size_t)bh * 4096 + d * 64);
#pragma unroll
    for (int e2 = 0; e2 < 32; ++e2)
      Ao[e2] = __floats2half2_rn(row[2 * e2] * inv, row[2 * e2 + 1] * inv);
  }
}

// ---------------------------------------------------------------------------
// Tensor-core attnv: Z[n][d] = sum_e v[n][e] attn[d][e]. Both operands in
// natural layout (non-trans ldsm). CTA = 256 tokens of one (b,h).
// ---------------------------------------------------------------------------
__global__ __launch_bounds__(256) void attnv_tc_kernel() {
  __shared__ __align__(16) __half vt[256 * 64];  // 32KB, swizzled
  __shared__ __align__(16) __half at[64 * 64];   // 8KB, swizzled
  const int bh = blockIdx.y, b = bh >> 4, h = bh & 15;
  const int tb = blockIdx.x * 256;               // token block
  const int tid = threadIdx.x, lane = tid & 31, wid = tid >> 5;
  const int wm = wid & 3, wd = wid >> 2;
  const uint32_t vb = smem_u32(vt), ab = smem_u32(at);

  const __half* Vg = g_Yh + (size_t)(b * NN + tb) * QKV_COLS + 2 * CC + h * DH;
#pragma unroll
  for (int i = 0; i < 8; ++i) {
    int idx = tid + i * 256;
    int r = idx >> 3, g = idx & 7;
    cp_async16(vb + r * 128 + ((g ^ (r & 7)) << 4), Vg + (size_t)r * QKV_COLS + g * 8);
  }
  const __half* Ag = g_attnh + (size_t)bh * 4096;
#pragma unroll
  for (int i = 0; i < 2; ++i) {
    int idx = tid + i * 256;
    int r = idx >> 3, g = idx & 7;
    cp_async16(ab + r * 128 + ((g ^ (r & 7)) << 4), Ag + r * 64 + g * 8);
  }
  asm volatile("cp.async.commit_group;");
  asm volatile("cp.async.wait_group 0;");
  __syncthreads();

  float acc[4][4][4] = {};     // mi(token 16) x dj(d 8) x frag
#pragma unroll
  for (int ks = 0; ks < 4; ++ks) {
    const int ge0 = ks * 2;
    uint32_t a[4][4], bf[4][2];
#pragma unroll
    for (int mi = 0; mi < 4; ++mi) {
      int tok = wm * 64 + mi * 16 + (lane & 7) + (((lane >> 3) & 1) << 3);
      int gg = ge0 + (lane >> 4);
      ldsm_x4(a[mi], vb + tok * 128 + ((gg ^ (tok & 7)) << 4));
    }
#pragma unroll
    for (int dj = 0; dj < 4; ++dj) {
      int d = wd * 32 + dj * 8 + (lane & 7);
      int gg = ge0 + ((lane >> 3) & 1);
      ldsm_x2(bf[dj], ab + d * 128 + ((gg ^ (d & 7)) << 4));
    }
#pragma unroll
    for (int mi = 0; mi < 4; ++mi)
#pragma unroll
      for (int dj = 0; dj < 4; ++dj)
        mma_f16(acc[mi][dj], a[mi], bf[dj][0], bf[dj][1]);
  }

  const int rr = lane >> 2, cc2 = (lane & 3) * 2;
#pragma unroll
  for (int mi = 0; mi < 4; ++mi) {
    size_t tok = (size_t)(b * NN + tb + wm * 64 + mi * 16 + rr);
#pragma unroll
    for (int dj = 0; dj < 4; ++dj) {
      size_t col = h * DH + wd * 32 + dj * 8 + cc2;
      *(__half2*)(g_Zh + tok * CC + col) =
          __floats2half2_rn(acc[mi][dj][0], acc[mi][dj][1]);
      *(__half2*)(g_Zh + (tok + 8) * CC + col) =
          __floats2half2_rn(acc[mi][dj][2], acc[mi][dj][3]);
    }
  }
}

// ---------------------------------------------------------------------------
extern "C" void kernel_launch(void* const* d_in, const int* in_sizes, int n_in,
                              void* d_out, int out_size) {
  const float* x      = (const float*)d_in[0];
  const float* w_qkv  = (const float*)d_in[1];
  const float* temp   = (const float*)d_in[2];
  const float* w_proj = (const float*)d_in[3];
  const float* b_proj = (const float*)d_in[4];
  float* out = (float*)d_out;

  static __half *Yh = nullptr, *Ah = nullptr, *Wh = nullptr, *Zh = nullptr;
  if (Yh == nullptr) {
    cudaGetSymbolAddress((void**)&Yh, g_Yh);
    cudaGetSymbolAddress((void**)&Zh, g_Zh);
    cudaGetSymbolAddress((void**)&Ah, g_Af16);
    cudaGetSymbolAddress((void**)&Wh, g_Wf16);
    cudaFuncSetAttribute((const void*)hgemm<1, 1>,
                         cudaFuncAttributeMaxDynamicSharedMemorySize, HGEMM_SMEM);
    cudaFuncSetAttribute((const void*)hgemm<0, 0>,
                         cudaFuncAttributeMaxDynamicSharedMemorySize, HGEMM_SMEM);
  }

  // prep
  f2h_kernel<<<(size_t)M_ROWS * CC / 2048, 256>>>(x, Ah);
  wtrans_kernel<<<dim3(QKV_COLS / 32, CC / 32), 256>>>(w_qkv, Wh, CC, QKV_COLS);

  // K1: qkv = x @ w_qkv -> fp16 Yh, + sumsq partials
  hgemm<1, 1><<<dim3(QKV_COLS / 256, M_ROWS / 128), 256, HGEMM_SMEM>>>(
      Ah, Wh, Yh, nullptr, QKV_COLS, CC);

  sumsq_reduce<<<dim3(8, BB), 256>>>();
  gramsm_kernel<<<BB * HH, 256, GRSM_SMEM>>>(temp);
  attnv_tc_kernel<<<dim3(NN / 256, BB * HH), 256>>>();

  // K5
  wtrans_kernel<<<dim3(CC / 32, CC / 32), 256>>>(w_proj, Wh, CC, CC);
  hgemm<0, 0><<<dim3(CC / 256, M_ROWS / 128), 256, HGEMM_SMEM>>>(
      Zh, Wh, out, b_proj, CC, CC);
}

// round 10
// speedup vs baseline: 7.6963x; 1.1289x over previous
#include <cuda_runtime.h>
#include <cuda_fp16.h>
#include <math.h>
#include <stdint.h>

// Problem constants: B=8, N=4096, C=1024, H=16, dh=64
#define BB 8
#define NN 4096
#define CC 1024
#define HH 16
#define DH 64
#define M_ROWS (BB * NN)          // 32768
#define QKV_COLS (3 * CC)         // 3072

// ---------------- static scratch -------------------------------------------
__device__ __align__(128) __half g_Yh[(size_t)M_ROWS * QKV_COLS];  // qkv fp16
__device__ __align__(128) __half g_Zh[(size_t)M_ROWS * CC];        // attn@v fp16
__device__ __align__(128) __half g_attnh[(size_t)BB * HH * DH * DH]; // attn fp16 [bh][d][e]
__device__ __align__(128) float g_sumsq[BB * 2 * CC];
__device__ __align__(128) float g_sspart[(size_t)(M_ROWS / 128) * 2048];
__device__ __align__(128) __half g_Af16[(size_t)M_ROWS * CC];      // x fp16 [M,K]
__device__ __align__(128) __half g_Wf16[(size_t)QKV_COLS * CC];    // W^T fp16 [N,K]

// ============================ helpers =======================================
__device__ __forceinline__ uint32_t smem_u32(const void* p) {
  uint32_t a;
  asm("{ .reg .u64 t; cvta.to.shared.u64 t, %1; cvt.u32.u64 %0, t; }" : "=r"(a) : "l"(p));
  return a;
}
__device__ __forceinline__ void cp_async16(uint32_t dst, const void* src) {
  asm volatile("cp.async.cg.shared.global [%0], [%1], 16;" :: "r"(dst), "l"(src));
}
__device__ __forceinline__ void ldsm_x4(uint32_t* r, uint32_t addr) {
  asm volatile("ldmatrix.sync.aligned.m8n8.x4.shared.b16 {%0,%1,%2,%3}, [%4];"
               : "=r"(r[0]), "=r"(r[1]), "=r"(r[2]), "=r"(r[3]) : "r"(addr));
}
__device__ __forceinline__ void ldsm_x4_t(uint32_t* r, uint32_t addr) {
  asm volatile("ldmatrix.sync.aligned.m8n8.x4.trans.shared.b16 {%0,%1,%2,%3}, [%4];"
               : "=r"(r[0]), "=r"(r[1]), "=r"(r[2]), "=r"(r[3]) : "r"(addr));
}
__device__ __forceinline__ void ldsm_x2(uint32_t* r, uint32_t addr) {
  asm volatile("ldmatrix.sync.aligned.m8n8.x2.shared.b16 {%0,%1}, [%2];"
               : "=r"(r[0]), "=r"(r[1]) : "r"(addr));
}
__device__ __forceinline__ void ldsm_x2_t(uint32_t* r, uint32_t addr) {
  asm volatile("ldmatrix.sync.aligned.m8n8.x2.trans.shared.b16 {%0,%1}, [%2];"
               : "=r"(r[0]), "=r"(r[1]) : "r"(addr));
}
__device__ __forceinline__ void mma_f16(float* c, const uint32_t* a, uint32_t b0,
                                        uint32_t b1) {
  asm volatile(
      "mma.sync.aligned.m16n8k16.row.col.f32.f16.f16.f32 "
      "{%0,%1,%2,%3}, {%4,%5,%6,%7}, {%8,%9}, {%0,%1,%2,%3};"
      : "+f"(c[0]), "+f"(c[1]), "+f"(c[2]), "+f"(c[3])
      : "r"(a[0]), "r"(a[1]), "r"(a[2]), "r"(a[3]), "r"(b0), "r"(b1));
}

// ---------------------------------------------------------------------------
// fp16 tensor-core GEMM: C[M,N] = A[M,K] @ W[N,K]^T, CTA tile 128x256,
// 512 threads (16 warps: 2(M) x 8(N)), warp tile 64x32, BK=64, 3-stage
// cp.async pipeline. OUT_HALF: fp16 out. SUMSQ: per-(Mtile,col) sumsq.
// ---------------------------------------------------------------------------
#define HSTAGE 49152
#define HGEMM_SMEM (3 * HSTAGE)          // 144KB

template <int OUT_HALF, int SUMSQ>
__global__ __launch_bounds__(512) void hgemm(
    const __half* __restrict__ A, const __half* __restrict__ Bt,
    void* __restrict__ Cv, const float* __restrict__ bias, int N, int K) {
  extern __shared__ char smembuf[];
  const uint32_t sbase = smem_u32(smembuf);
  const int tid = threadIdx.x, lane = tid & 31, wid = tid >> 5;
  const int wm = wid & 1, wn = wid >> 1;   // 2 x 8 warp grid
  const size_t bm = (size_t)blockIdx.y * 128;
  const size_t bn = (size_t)blockIdx.x * 256;

  float acc[4][4][4];
#pragma unroll
  for (int mi = 0; mi < 4; ++mi)
#pragma unroll
    for (int nj = 0; nj < 4; ++nj)
#pragma unroll
      for (int j = 0; j < 4; ++j) acc[mi][nj][j] = 0.0f;

  auto issue_loads = [&](int kt, int st) {
    const uint32_t sA = sbase + st * HSTAGE;
    const uint32_t sB = sA + 16384;
    const __half* Ag = A + bm * K + kt * 64;
    const __half* Bg = Bt + bn * K + kt * 64;
#pragma unroll
    for (int i = 0; i < 2; ++i) {          // A: 1024 granules
      int idx = tid + i * 512;
      int r = idx >> 3, g = idx & 7;
      cp_async16(sA + r * 128 + ((g ^ (r & 7)) << 4), Ag + (size_t)r * K + g * 8);
    }
#pragma unroll
    for (int i = 0; i < 4; ++i) {          // B: 2048 granules
      int idx = tid + i * 512;
      int r = idx >> 3, g = idx & 7;
      cp_async16(sB + r * 128 + ((g ^ (r & 7)) << 4), Bg + (size_t)r * K + g * 8);
    }
    asm volatile("cp.async.commit_group;");
  };

  const int nt = K >> 6;
  issue_loads(0, 0);
  if (nt > 1) issue_loads(1, 1);

  const int hi8 = (lane >> 4) & 1;
  const int rsel = lane & 15;

  for (int kt = 0; kt < nt; ++kt) {
    if (kt + 1 < nt) {
      asm volatile("cp.async.wait_group 1;");
    } else {
      asm volatile("cp.async.wait_group 0;");
    }
    __syncthreads();
    if (kt + 2 < nt) issue_loads(kt + 2, (kt + 2) % 3);

    const int st = kt % 3;
    const uint32_t sA = sbase + st * HSTAGE;
    const uint32_t sB = sA + 16384;
#pragma unroll
    for (int ks = 0; ks < 4; ++ks) {
      const int g16 = 2 * ks + hi8;
      uint32_t a[4][4], b[2][4];
#pragma unroll
      for (int mi = 0; mi < 4; ++mi) {
        int mrow = wm * 64 + mi * 16 + rsel;
        ldsm_x4(a[mi], sA + mrow * 128 + ((g16 ^ (mrow & 7)) << 4));
      }
#pragma unroll
      for (int nb = 0; nb < 2; ++nb) {
        int nrow = wn * 32 + nb * 16 + rsel;
        ldsm_x4(b[nb], sB + nrow * 128 + ((g16 ^ (nrow & 7)) << 4));
      }
#pragma unroll
      for (int mi = 0; mi < 4; ++mi)
#pragma unroll
        for (int nj = 0; nj < 4; ++nj)
          mma_f16(acc[mi][nj], a[mi], b[nj >> 1][nj & 1], b[nj >> 1][(nj & 1) + 2]);
    }
  }

  const int rr = lane >> 2, cc2 = (lane & 3) * 2;
#pragma unroll
  for (int mi = 0; mi < 4; ++mi) {
    size_t row = bm + wm * 64 + mi * 16 + rr;
#pragma unroll
    for (int nj = 0; nj < 4; ++nj) {
      size_t col = bn + wn * 32 + nj * 8 + cc2;
      if (OUT_HALF) {
        __half* C = (__half*)Cv;
        *(__half2*)(C + row * N + col) =
            __floats2half2_rn(acc[mi][nj][0], acc[mi][nj][1]);
        *(__half2*)(C + (row + 8) * N + col) =
            __floats2half2_rn(acc[mi][nj][2], acc[mi][nj][3]);
      } else {
        float* C = (float*)Cv;
        float b0 = 0.0f, b1 = 0.0f;
        if (bias) { b0 = bias[col]; b1 = bias[col + 1]; }
        *(float2*)(C + row * N + col) =
            make_float2(acc[mi][nj][0] + b0, acc[mi][nj][1] + b1);
        *(float2*)(C + (row + 8) * N + col) =
            make_float2(acc[mi][nj][2] + b0, acc[mi][nj][3] + b1);
      }
    }
  }

  if (SUMSQ) {
    if (bn < 2048) {
      __syncthreads();
      float* sq = (float*)smembuf;          // [256 cols][16 slots] = 16KB
      const int slot = wm * 8 + rr;
#pragma unroll
      for (int nj = 0; nj < 4; ++nj) {
        int c0 = wn * 32 + nj * 8 + cc2;
        float p0 = 0.0f, p1 = 0.0f;
#pragma unroll
        for (int mi = 0; mi < 4; ++mi) {
          p0 += acc[mi][nj][0] * acc[mi][nj][0] + acc[mi][nj][2] * acc[mi][nj][2];
          p1 += acc[mi][nj][1] * acc[mi][nj][1] + acc[mi][nj][3] * acc[mi][nj][3];
        }
        sq[c0 * 16 + slot] = p0;
        sq[(c0 + 1) * 16 + slot] = p1;
      }
      __syncthreads();
      if (tid < 256) {
        float s = 0.0f;
#pragma unroll
        for (int j = 0; j < 16; ++j) s += sq[tid * 16 + j];
        g_sspart[(size_t)blockIdx.y * 2048 + bn + tid] = s;
      }
    }
  }
}

// ---------------------------------------------------------------------------
// Reduce per-Mtile sumsq partials -> g_sumsq. Deterministic order.
// ---------------------------------------------------------------------------
__global__ __launch_bounds__(256) void sumsq_reduce() {
  const int c = blockIdx.x * 256 + threadIdx.x;
  const int b = blockIdx.y;
  float s = 0.0f;
#pragma unroll
  for (int t = 0; t < 32; ++t)
    s += g_sspart[(size_t)(b * 32 + t) * 2048 + c];
  g_sumsq[b * 2048 + c] = s;
}

// ---------------------------------------------------------------------------
__global__ __launch_bounds__(256) void f2h_kernel(const float* __restrict__ A,
                                                  __half* __restrict__ O) {
  size_t i = ((size_t)blockIdx.x * 256 + threadIdx.x) * 8;
  float4 v0 = *(const float4*)(A + i);
  float4 v1 = *(const float4*)(A + i + 4);
  union { __half2 h[4]; uint4 u; } o;
  o.h[0] = __floats2half2_rn(v0.x, v0.y);
  o.h[1] = __floats2half2_rn(v0.z, v0.w);
  o.h[2] = __floats2half2_rn(v1.x, v1.y);
  o.h[3] = __floats2half2_rn(v1.z, v1.w);
  *(uint4*)(O + i) = o.u;
}

// ---------------------------------------------------------------------------
__global__ __launch_bounds__(256) void wtrans_kernel(const float* __restrict__ W,
                                                     __half* __restrict__ O,
                                                     int K, int N) {
  __shared__ float s[32][33];
  const int n0 = blockIdx.x * 32, k0 = blockIdx.y * 32;
  const int tx = threadIdx.x & 31, tg = threadIdx.x >> 5;
#pragma unroll
  for (int j = 0; j < 4; ++j) {
    int kr = tg + j * 8;
    s[kr][tx] = W[(size_t)(k0 + kr) * N + n0 + tx];
  }
  __syncthreads();
#pragma unroll
  for (int j = 0; j < 4; ++j) {
    int nr = tg + j * 8;
    O[(size_t)(n0 + nr) * K + k0 + tx] = __float2half_rn(s[tx][nr]);
  }
}

// ---------------------------------------------------------------------------
// Fused gram + softmax per (b,h), 3-stage pipelined loads.
// ---------------------------------------------------------------------------
#define GRSM_STAGE 32768                 // q 16KB + k 16KB
#define GRSM_SMEM (3 * GRSM_STAGE)       // 96KB; S (64x68 fp32) overlays after

__global__ __launch_bounds__(256) void gramsm_kernel(const float* __restrict__ temp) {
  extern __shared__ char gsm[];
  __shared__ float nq[64], nk[64];
  const uint32_t sbase = smem_u32(gsm);
  const int bh = blockIdx.x, b = bh >> 4, h = bh & 15;
  const int tid = threadIdx.x, lane = tid & 31, wid = tid >> 5;
  const __half* Yq = g_Yh + (size_t)b * NN * QKV_COLS + h * DH;
  const __half* Yk = Yq + CC;

  float acc[4][4] = {};
  const int e0 = wid * 8;

  auto issue_chunk = [&](int ch, int st) {
    const uint32_t qb = sbase + st * GRSM_STAGE;
    const uint32_t kb = qb + 16384;
#pragma unroll
    for (int i = 0; i < 4; ++i) {
      int idx = tid + i * 256;
      int r = idx >> 3, g = idx & 7;
      size_t go = (size_t)(ch * 128 + r) * QKV_COLS + g * 8;
      uint32_t so = r * 128 + ((g ^ (r & 7)) << 4);
      cp_async16(qb + so, Yq + go);
      cp_async16(kb + so, Yk + go);
    }
    asm volatile("cp.async.commit_group;");
  };

  issue_chunk(0, 0);
  issue_chunk(1, 1);

  for (int ch = 0; ch < 32; ++ch) {
    if (ch + 1 < 32) {
      asm volatile("cp.async.wait_group 1;");
    } else {
      asm volatile("cp.async.wait_group 0;");
    }
    __syncthreads();
    if (ch + 2 < 32) issue_chunk(ch + 2, (ch + 2) % 3);

    const uint32_t qb = sbase + (ch % 3) * GRSM_STAGE;
    const uint32_t kb = qb + 16384;
#pragma unroll
    for (int s = 0; s < 8; ++s) {
      const int tokA = s * 16 + (lane & 7) + ((lane >> 4) << 3);
      uint32_t a[4][4];
#pragma unroll
      for (int mi = 0; mi < 4; ++mi) {
        int gd = mi * 2 + ((lane >> 3) & 1);
        ldsm_x4_t(a[mi], qb + tokA * 128 + ((gd ^ (tokA & 7)) << 4));
      }
      const int tokB = s * 16 + (lane & 7) + (((lane >> 3) & 1) << 3);
      uint32_t bf[2];
      ldsm_x2_t(bf, kb + tokB * 128 + ((wid ^ (tokB & 7)) << 4));
#pragma unroll
      for (int mi = 0; mi < 4; ++mi)
        mma_f16(acc[mi], a[mi], bf[0], bf[1]);
    }
  }
  __syncthreads();

  if (tid < 64) {
    nq[tid] = fmaxf(sqrtf(g_sumsq[b * 2048 + h * DH + tid]), 1e-12f);
    nk[tid] = fmaxf(sqrtf(g_sumsq[b * 2048 + CC + h * DH + tid]), 1e-12f);
  }

  float* S = (float*)gsm;      // [64][68]
  const int rr = lane >> 2, cc2 = (lane & 3) * 2;
#pragma unroll
  for (int mi = 0; mi < 4; ++mi) {
    S[(mi * 16 + rr) * 68 + e0 + cc2]     = acc[mi][0];
    S[(mi * 16 + rr) * 68 + e0 + cc2 + 1] = acc[mi][1];
    S[(mi * 16 + 8 + rr) * 68 + e0 + cc2]     = acc[mi][2];
    S[(mi * 16 + 8 + rr) * 68 + e0 + cc2 + 1] = acc[mi][3];
  }
  __syncthreads();

  if (tid < 64) {
    const int d = tid;
    const float sc = temp[h] / nq[d];
    float row[64];
    float m = -3.402823466e38f;
#pragma unroll
    for (int e = 0; e < 64; ++e) {
      row[e] = S[d * 68 + e] * sc / nk[e];
      m = fmaxf(m, row[e]);
    }
    float sum = 0.0f;
#pragma unroll
    for (int e = 0; e < 64; ++e) {
      row[e] = expf(row[e] - m);
      sum += row[e];
    }
    const float inv = 1.0f / sum;
    __half2* Ao = (__half2*)(g_attnh + (size_t)bh * 4096 + d * 64);
#pragma unroll
    for (int e2 = 0; e2 < 32; ++e2)
      Ao[e2] = __floats2half2_rn(row[2 * e2] * inv, row[2 * e2 + 1] * inv);
  }
}

// ---------------------------------------------------------------------------
// Tensor-core attnv: Z[n][d] = sum_e v[n][e] attn[d][e].
// ---------------------------------------------------------------------------
__global__ __launch_bounds__(256) void attnv_tc_kernel() {
  __shared__ __align__(16) __half vt[256 * 64];
  __shared__ __align__(16) __half at[64 * 64];
  const int bh = blockIdx.y, b = bh >> 4, h = bh & 15;
  const int tb = blockIdx.x * 256;
  const int tid = threadIdx.x, lane = tid & 31, wid = tid >> 5;
  const int wm = wid & 3, wd = wid >> 2;
  const uint32_t vb = smem_u32(vt), ab = smem_u32(at);

  const __half* Vg = g_Yh + (size_t)(b * NN + tb) * QKV_COLS + 2 * CC + h * DH;
#pragma unroll
  for (int i = 0; i < 8; ++i) {
    int idx = tid + i * 256;
    int r = idx >> 3, g = idx & 7;
    cp_async16(vb + r * 128 + ((g ^ (r & 7)) << 4), Vg + (size_t)r * QKV_COLS + g * 8);
  }
  const __half* Ag = g_attnh + (size_t)bh * 4096;
#pragma unroll
  for (int i = 0; i < 2; ++i) {
    int idx = tid + i * 256;
    int r = idx >> 3, g = idx & 7;
    cp_async16(ab + r * 128 + ((g ^ (r & 7)) << 4), Ag + r * 64 + g * 8);
  }
  asm volatile("cp.async.commit_group;");
  asm volatile("cp.async.wait_group 0;");
  __syncthreads();

  float acc[4][4][4] = {};
#pragma unroll
  for (int ks = 0; ks < 4; ++ks) {
    const int ge0 = ks * 2;
    uint32_t a[4][4], bf[4][2];
#pragma unroll
    for (int mi = 0; mi < 4; ++mi) {
      int tok = wm * 64 + mi * 16 + (lane & 7) + (((lane >> 3) & 1) << 3);
      int gg = ge0 + (lane >> 4);
      ldsm_x4(a[mi], vb + tok * 128 + ((gg ^ (tok & 7)) << 4));
    }
#pragma unroll
    for (int dj = 0; dj < 4; ++dj) {
      int d = wd * 32 + dj * 8 + (lane & 7);
      int gg = ge0 + ((lane >> 3) & 1);
      ldsm_x2(bf[dj], ab + d * 128 + ((gg ^ (d & 7)) << 4));
    }
#pragma unroll
    for (int mi = 0; mi < 4; ++mi)
#pragma unroll
      for (int dj = 0; dj < 4; ++dj)
        mma_f16(acc[mi][dj], a[mi], bf[dj][0], bf[dj][1]);
  }

  const int rr = lane >> 2, cc2 = (lane & 3) * 2;
#pragma unroll
  for (int mi = 0; mi < 4; ++mi) {
    size_t tok = (size_t)(b * NN + tb + wm * 64 + mi * 16 + rr);
#pragma unroll
    for (int dj = 0; dj < 4; ++dj) {
      size_t col = h * DH + wd * 32 + dj * 8 + cc2;
      *(__half2*)(g_Zh + tok * CC + col) =
          __floats2half2_rn(acc[mi][dj][0], acc[mi][dj][1]);
      *(__half2*)(g_Zh + (tok + 8) * CC + col) =
          __floats2half2_rn(acc[mi][dj][2], acc[mi][dj][3]);
    }
  }
}

// ---------------------------------------------------------------------------
extern "C" void kernel_launch(void* const* d_in, const int* in_sizes, int n_in,
                              void* d_out, int out_size) {
  const float* x      = (const float*)d_in[0];
  const float* w_qkv  = (const float*)d_in[1];
  const float* temp   = (const float*)d_in[2];
  const float* w_proj = (const float*)d_in[3];
  const float* b_proj = (const float*)d_in[4];
  float* out = (float*)d_out;

  static __half *Yh = nullptr, *Ah = nullptr, *Wh = nullptr, *Zh = nullptr;
  if (Yh == nullptr) {
    cudaGetSymbolAddress((void**)&Yh, g_Yh);
    cudaGetSymbolAddress((void**)&Zh, g_Zh);
    cudaGetSymbolAddress((void**)&Ah, g_Af16);
    cudaGetSymbolAddress((void**)&Wh, g_Wf16);
    cudaFuncSetAttribute((const void*)hgemm<1, 1>,
                         cudaFuncAttributeMaxDynamicSharedMemorySize, HGEMM_SMEM);
    cudaFuncSetAttribute((const void*)hgemm<0, 0>,
                         cudaFuncAttributeMaxDynamicSharedMemorySize, HGEMM_SMEM);
    cudaFuncSetAttribute((const void*)gramsm_kernel,
                         cudaFuncAttributeMaxDynamicSharedMemorySize, GRSM_SMEM);
  }

  // prep
  f2h_kernel<<<(size_t)M_ROWS * CC / 2048, 256>>>(x, Ah);
  wtrans_kernel<<<dim3(QKV_COLS / 32, CC / 32), 256>>>(w_qkv, Wh, CC, QKV_COLS);

  // K1: qkv = x @ w_qkv -> fp16 Yh, + sumsq partials
  hgemm<1, 1><<<dim3(QKV_COLS / 256, M_ROWS / 128), 512, HGEMM_SMEM>>>(
      Ah, Wh, Yh, nullptr, QKV_COLS, CC);

  sumsq_reduce<<<dim3(8, BB), 256>>>();
  gramsm_kernel<<<BB * HH, 256, GRSM_SMEM>>>(temp);
  attnv_tc_kernel<<<dim3(NN / 256, BB * HH), 256>>>();

  // K5
  wtrans_kernel<<<dim3(CC / 32, CC / 32), 256>>>(w_proj, Wh, CC, CC);
  hgemm<0, 0><<<dim3(CC / 256, M_ROWS / 128), 512, HGEMM_SMEM>>>(
      Zh, Wh, out, b_proj, CC, CC);
}

// round 12
// speedup vs baseline: 8.3555x; 1.0857x over previous
#include <cuda_runtime.h>
#include <cuda_fp16.h>
#include <math.h>
#include <stdint.h>

// Problem constants: B=8, N=4096, C=1024, H=16, dh=64
#define BB 8
#define NN 4096
#define CC 1024
#define HH 16
#define DH 64
#define M_ROWS (BB * NN)          // 32768
#define QKV_COLS (3 * CC)         // 3072

// ---------------- static scratch -------------------------------------------
__device__ __align__(128) __half g_Yh[(size_t)M_ROWS * QKV_COLS];  // qkv fp16
__device__ __align__(128) __half g_Zh[(size_t)M_ROWS * CC];        // attn@v fp16
__device__ __align__(128) __half g_attnh[(size_t)BB * HH * DH * DH]; // attn fp16 [bh][d][e]
__device__ __align__(128) float g_sumsq[BB * 2 * CC];
__device__ __align__(128) float g_sspart[(size_t)(M_ROWS / 128) * 2048];
__device__ __align__(128) __half g_Af16[(size_t)M_ROWS * CC];      // x fp16 [M,K]
__device__ __align__(128) __half g_Wf16[(size_t)QKV_COLS * CC];    // W^T fp16 [N,K]

// ============================ helpers =======================================
__device__ __forceinline__ uint32_t smem_u32(const void* p) {
  uint32_t a;
  asm("{ .reg .u64 t; cvta.to.shared.u64 t, %1; cvt.u32.u64 %0, t; }" : "=r"(a) : "l"(p));
  return a;
}
__device__ __forceinline__ void cp_async16(uint32_t dst, const void* src) {
  asm volatile("cp.async.cg.shared.global [%0], [%1], 16;" :: "r"(dst), "l"(src));
}
__device__ __forceinline__ void ldsm_x4(uint32_t* r, uint32_t addr) {
  asm volatile("ldmatrix.sync.aligned.m8n8.x4.shared.b16 {%0,%1,%2,%3}, [%4];"
               : "=r"(r[0]), "=r"(r[1]), "=r"(r[2]), "=r"(r[3]) : "r"(addr));
}
__device__ __forceinline__ void ldsm_x4_t(uint32_t* r, uint32_t addr) {
  asm volatile("ldmatrix.sync.aligned.m8n8.x4.trans.shared.b16 {%0,%1,%2,%3}, [%4];"
               : "=r"(r[0]), "=r"(r[1]), "=r"(r[2]), "=r"(r[3]) : "r"(addr));
}
__device__ __forceinline__ void ldsm_x2(uint32_t* r, uint32_t addr) {
  asm volatile("ldmatrix.sync.aligned.m8n8.x2.shared.b16 {%0,%1}, [%2];"
               : "=r"(r[0]), "=r"(r[1]) : "r"(addr));
}
__device__ __forceinline__ void ldsm_x2_t(uint32_t* r, uint32_t addr) {
  asm volatile("ldmatrix.sync.aligned.m8n8.x2.trans.shared.b16 {%0,%1}, [%2];"
               : "=r"(r[0]), "=r"(r[1]) : "r"(addr));
}
__device__ __forceinline__ void mma_f16(float* c, const uint32_t* a, uint32_t b0,
                                        uint32_t b1) {
  asm volatile(
      "mma.sync.aligned.m16n8k16.row.col.f32.f16.f16.f32 "
      "{%0,%1,%2,%3}, {%4,%5,%6,%7}, {%8,%9}, {%0,%1,%2,%3};"
      : "+f"(c[0]), "+f"(c[1]), "+f"(c[2]), "+f"(c[3])
      : "r"(a[0]), "r"(a[1]), "r"(a[2]), "r"(a[3]), "r"(b0), "r"(b1));
}

// ---------------------------------------------------------------------------
// fp16 tensor-core GEMM: C[M,N] = A[M,K] @ W[N,K]^T. CTA tile 128x128,
// 256 threads (8 warps: 2(M) x 4(N)), warp tile 64x32, BK=64, 3-stage
// cp.async pipeline, 96KB smem -> 2 CTAs/SM (independent barrier domains).
// OUT_HALF: fp16 out. SUMSQ: per-(Mtile,col) sumsq partials for cols<2048.
// ---------------------------------------------------------------------------
#define HSTAGE 32768                     // A 16KB + B 16KB
#define HGEMM_SMEM (3 * HSTAGE)          // 96KB

template <int OUT_HALF, int SUMSQ>
__global__ __launch_bounds__(256, 2) void hgemm(
    const __half* __restrict__ A, const __half* __restrict__ Bt,
    void* __restrict__ Cv, const float* __restrict__ bias, int N, int K) {
  extern __shared__ char smembuf[];
  const uint32_t sbase = smem_u32(smembuf);
  const int tid = threadIdx.x, lane = tid & 31, wid = tid >> 5;
  const int wm = wid & 1, wn = wid >> 1;   // 2 x 4 warp grid
  const size_t bm = (size_t)blockIdx.y * 128;
  const size_t bn = (size_t)blockIdx.x * 128;

  float acc[4][4][4];
#pragma unroll
  for (int mi = 0; mi < 4; ++mi)
#pragma unroll
    for (int nj = 0; nj < 4; ++nj)
#pragma unroll
      for (int j = 0; j < 4; ++j) acc[mi][nj][j] = 0.0f;

  auto issue_loads = [&](int kt, int st) {
    const uint32_t sA = sbase + st * HSTAGE;
    const uint32_t sB = sA + 16384;
    const __half* Ag = A + bm * K + kt * 64;
    const __half* Bg = Bt + bn * K + kt * 64;
#pragma unroll
    for (int i = 0; i < 4; ++i) {          // A: 1024 granules
      int idx = tid + i * 256;
      int r = idx >> 3, g = idx & 7;
      cp_async16(sA + r * 128 + ((g ^ (r & 7)) << 4), Ag + (size_t)r * K + g * 8);
    }
#pragma unroll
    for (int i = 0; i < 4; ++i) {          // B: 1024 granules
      int idx = tid + i * 256;
      int r = idx >> 3, g = idx & 7;
      cp_async16(sB + r * 128 + ((g ^ (r & 7)) << 4), Bg + (size_t)r * K + g * 8);
    }
    asm volatile("cp.async.commit_group;");
  };

  const int nt = K >> 6;
  issue_loads(0, 0);
  if (nt > 1) issue_loads(1, 1);

  const int hi8 = (lane >> 4) & 1;
  const int rsel = lane & 15;

  for (int kt = 0; kt < nt; ++kt) {
    if (kt + 1 < nt) {
      asm volatile("cp.async.wait_group 1;");
    } else {
      asm volatile("cp.async.wait_group 0;");
    }
    __syncthreads();
    if (kt + 2 < nt) issue_loads(kt + 2, (kt + 2) % 3);

    const int st = kt % 3;
    const uint32_t sA = sbase + st * HSTAGE;
    const uint32_t sB = sA + 16384;
#pragma unroll
    for (int ks = 0; ks < 4; ++ks) {
      const int g16 = 2 * ks + hi8;
      uint32_t a[4][4], b[2][4];
#pragma unroll
      for (int mi = 0; mi < 4; ++mi) {
        int mrow = wm * 64 + mi * 16 + rsel;
        ldsm_x4(a[mi], sA + mrow * 128 + ((g16 ^ (mrow & 7)) << 4));
      }
#pragma unroll
      for (int nb = 0; nb < 2; ++nb) {
        int nrow = wn * 32 + nb * 16 + rsel;
        ldsm_x4(b[nb], sB + nrow * 128 + ((g16 ^ (nrow & 7)) << 4));
      }
#pragma unroll
      for (int mi = 0; mi < 4; ++mi)
#pragma unroll
        for (int nj = 0; nj < 4; ++nj)
          mma_f16(acc[mi][nj], a[mi], b[nj >> 1][nj & 1], b[nj >> 1][(nj & 1) + 2]);
    }
  }

  const int rr = lane >> 2, cc2 = (lane & 3) * 2;
#pragma unroll
  for (int mi = 0; mi < 4; ++mi) {
    size_t row = bm + wm * 64 + mi * 16 + rr;
#pragma unroll
    for (int nj = 0; nj < 4; ++nj) {
      size_t col = bn + wn * 32 + nj * 8 + cc2;
      if (OUT_HALF) {
        __half* C = (__half*)Cv;
        *(__half2*)(C + row * N + col) =
            __floats2half2_rn(acc[mi][nj][0], acc[mi][nj][1]);
        *(__half2*)(C + (row + 8) * N + col) =
            __floats2half2_rn(acc[mi][nj][2], acc[mi][nj][3]);
      } else {
        float* C = (float*)Cv;
        float b0 = 0.0f, b1 = 0.0f;
        if (bias) { b0 = bias[col]; b1 = bias[col + 1]; }
        *(float2*)(C + row * N + col) =
            make_float2(acc[mi][nj][0] + b0, acc[mi][nj][1] + b1);
        *(float2*)(C + (row + 8) * N + col) =
            make_float2(acc[mi][nj][2] + b0, acc[mi][nj][3] + b1);
      }
    }
  }

  if (SUMSQ) {
    if (bn < 2048) {
      __syncthreads();
      float* sq = (float*)smembuf;          // [128 cols][16 slots] = 8KB
      const int slot = wm * 8 + rr;
#pragma unroll
      for (int nj = 0; nj < 4; ++nj) {
        int c0 = wn * 32 + nj * 8 + cc2;
        float p0 = 0.0f, p1 = 0.0f;
#pragma unroll
        for (int mi = 0; mi < 4; ++mi) {
          p0 += acc[mi][nj][0] * acc[mi][nj][0] + acc[mi][nj][2] * acc[mi][nj][2];
          p1 += acc[mi][nj][1] * acc[mi][nj][1] + acc[mi][nj][3] * acc[mi][nj][3];
        }
        sq[c0 * 16 + slot] = p0;
        sq[(c0 + 1) * 16 + slot] = p1;
      }
      __syncthreads();
      if (tid < 128) {
        float s = 0.0f;
#pragma unroll
        for (int j = 0; j < 16; ++j) s += sq[tid * 16 + j];
        g_sspart[(size_t)blockIdx.y * 2048 + bn + tid] = s;
      }
    }
  }
}

// ---------------------------------------------------------------------------
// Reduce per-Mtile sumsq partials -> g_sumsq. Deterministic order.
// ---------------------------------------------------------------------------
__global__ __launch_bounds__(256) void sumsq_reduce() {
  const int c = blockIdx.x * 256 + threadIdx.x;
  const int b = blockIdx.y;
  float s = 0.0f;
#pragma unroll
  for (int t = 0; t < 32; ++t)
    s += g_sspart[(size_t)(b * 32 + t) * 2048 + c];
  g_sumsq[b * 2048 + c] = s;
}

// ---------------------------------------------------------------------------
__global__ __launch_bounds__(256) void f2h_kernel(const float* __restrict__ A,
                                                  __half* __restrict__ O) {
  size_t i = ((size_t)blockIdx.x * 256 + threadIdx.x) * 8;
  float4 v0 = *(const float4*)(A + i);
  float4 v1 = *(const float4*)(A + i + 4);
  union { __half2 h[4]; uint4 u; } o;
  o.h[0] = __floats2half2_rn(v0.x, v0.y);
  o.h[1] = __floats2half2_rn(v0.z, v0.w);
  o.h[2] = __floats2half2_rn(v1.x, v1.y);
  o.h[3] = __floats2half2_rn(v1.z, v1.w);
  *(uint4*)(O + i) = o.u;
}

// ---------------------------------------------------------------------------
__global__ __launch_bounds__(256) void wtrans_kernel(const float* __restrict__ W,
                                                     __half* __restrict__ O,
                                                     int K, int N) {
  __shared__ float s[32][33];
  const int n0 = blockIdx.x * 32, k0 = blockIdx.y * 32;
  const int tx = threadIdx.x & 31, tg = threadIdx.x >> 5;
#pragma unroll
  for (int j = 0; j < 4; ++j) {
    int kr = tg + j * 8;
    s[kr][tx] = W[(size_t)(k0 + kr) * N + n0 + tx];
  }
  __syncthreads();
#pragma unroll
  for (int j = 0; j < 4; ++j) {
    int nr = tg + j * 8;
    O[(size_t)(n0 + nr) * K + k0 + tx] = __float2half_rn(s[tx][nr]);
  }
}

// ---------------------------------------------------------------------------
// Fused gram + softmax per (b,h), 3-stage pipelined loads.
// ---------------------------------------------------------------------------
#define GRSM_STAGE 32768                 // q 16KB + k 16KB
#define GRSM_SMEM (3 * GRSM_STAGE)       // 96KB; S (64x68 fp32) overlays after

__global__ __launch_bounds__(256) void gramsm_kernel(const float* __restrict__ temp) {
  extern __shared__ char gsm[];
  __shared__ float nq[64], nk[64];
  const uint32_t sbase = smem_u32(gsm);
  const int bh = blockIdx.x, b = bh >> 4, h = bh & 15;
  const int tid = threadIdx.x, lane = tid & 31, wid = tid >> 5;
  const __half* Yq = g_Yh + (size_t)b * NN * QKV_COLS + h * DH;
  const __half* Yk = Yq + CC;

  float acc[4][4] = {};
  const int e0 = wid * 8;

  auto issue_chunk = [&](int ch, int st) {
    const uint32_t qb = sbase + st * GRSM_STAGE;
    const uint32_t kb = qb + 16384;
#pragma unroll
    for (int i = 0; i < 4; ++i) {
      int idx = tid + i * 256;
      int r = idx >> 3, g = idx & 7;
      size_t go = (size_t)(ch * 128 + r) * QKV_COLS + g * 8;
      uint32_t so = r * 128 + ((g ^ (r & 7)) << 4);
      cp_async16(qb + so, Yq + go);
      cp_async16(kb + so, Yk + go);
    }
    asm volatile("cp.async.commit_group;");
  };

  issue_chunk(0, 0);
  issue_chunk(1, 1);

  for (int ch = 0; ch < 32; ++ch) {
    if (ch + 1 < 32) {
      asm volatile("cp.async.wait_group 1;");
    } else {
      asm volatile("cp.async.wait_group 0;");
    }
    __syncthreads();
    if (ch + 2 < 32) issue_chunk(ch + 2, (ch + 2) % 3);

    const uint32_t qb = sbase + (ch % 3) * GRSM_STAGE;
    const uint32_t kb = qb + 16384;
#pragma unroll
    for (int s = 0; s < 8; ++s) {
      const int tokA = s * 16 + (lane & 7) + ((lane >> 4) << 3);
      uint32_t a[4][4];
#pragma unroll
      for (int mi = 0; mi < 4; ++mi) {
        int gd = mi * 2 + ((lane >> 3) & 1);
        ldsm_x4_t(a[mi], qb + tokA * 128 + ((gd ^ (tokA & 7)) << 4));
      }
      const int tokB = s * 16 + (lane & 7) + (((lane >> 3) & 1) << 3);
      uint32_t bf[2];
      ldsm_x2_t(bf, kb + tokB * 128 + ((wid ^ (tokB & 7)) << 4));
#pragma unroll
      for (int mi = 0; mi < 4; ++mi)
        mma_f16(acc[mi], a[mi], bf[0], bf[1]);
    }
  }
  __syncthreads();

  if (tid < 64) {
    nq[tid] = fmaxf(sqrtf(g_sumsq[b * 2048 + h * DH + tid]), 1e-12f);
    nk[tid] = fmaxf(sqrtf(g_sumsq[b * 2048 + CC + h * DH + tid]), 1e-12f);
  }

  float* S = (float*)gsm;      // [64][68]
  const int rr = lane >> 2, cc2 = (lane & 3) * 2;
#pragma unroll
  for (int mi = 0; mi < 4; ++mi) {
    S[(mi * 16 + rr) * 68 + e0 + cc2]     = acc[mi][0];
    S[(mi * 16 + rr) * 68 + e0 + cc2 + 1] = acc[mi][1];
    S[(mi * 16 + 8 + rr) * 68 + e0 + cc2]     = acc[mi][2];
    S[(mi * 16 + 8 + rr) * 68 + e0 + cc2 + 1] = acc[mi][3];
  }
  __syncthreads();

  if (tid < 64) {
    const int d = tid;
    const float sc = temp[h] / nq[d];
    float row[64];
    float m = -3.402823466e38f;
#pragma unroll
    for (int e = 0; e < 64; ++e) {
      row[e] = S[d * 68 + e] * sc / nk[e];
      m = fmaxf(m, row[e]);
    }
    float sum = 0.0f;
#pragma unroll
    for (int e = 0; e < 64; ++e) {
      row[e] = expf(row[e] - m);
      sum += row[e];
    }
    const float inv = 1.0f / sum;
    __half2* Ao = (__half2*)(g_attnh + (size_t)bh * 4096 + d * 64);
#pragma unroll
    for (int e2 = 0; e2 < 32; ++e2)
      Ao[e2] = __floats2half2_rn(row[2 * e2] * inv, row[2 * e2 + 1] * inv);
  }
}

// ---------------------------------------------------------------------------
// Tensor-core attnv: Z[n][d] = sum_e v[n][e] attn[d][e].
// ---------------------------------------------------------------------------
__global__ __launch_bounds__(256) void attnv_tc_kernel() {
  __shared__ __align__(16) __half vt[256 * 64];
  __shared__ __align__(16) __half at[64 * 64];
  const int bh = blockIdx.y, b = bh >> 4, h = bh & 15;
  const int tb = blockIdx.x * 256;
  const int tid = threadIdx.x, lane = tid & 31, wid = tid >> 5;
  const int wm = wid & 3, wd = wid >> 2;
  const uint32_t vb = smem_u32(vt), ab = smem_u32(at);

  const __half* Vg = g_Yh + (size_t)(b * NN + tb) * QKV_COLS + 2 * CC + h * DH;
#pragma unroll
  for (int i = 0; i < 8; ++i) {
    int idx = tid + i * 256;
    int r = idx >> 3, g = idx & 7;
    cp_async16(vb + r * 128 + ((g ^ (r & 7)) << 4), Vg + (size_t)r * QKV_COLS + g * 8);
  }
  const __half* Ag = g_attnh + (size_t)bh * 4096;
#pragma unroll
  for (int i = 0; i < 2; ++i) {
    int idx = tid + i * 256;
    int r = idx >> 3, g = idx & 7;
    cp_async16(ab + r * 128 + ((g ^ (r & 7)) << 4), Ag + r * 64 + g * 8);
  }
  asm volatile("cp.async.commit_group;");
  asm volatile("cp.async.wait_group 0;");
  __syncthreads();

  float acc[4][4][4] = {};
#pragma unroll
  for (int ks = 0; ks < 4; ++ks) {
    const int ge0 = ks * 2;
    uint32_t a[4][4], bf[4][2];
#pragma unroll
    for (int mi = 0; mi < 4; ++mi) {
      int tok = wm * 64 + mi * 16 + (lane & 7) + (((lane >> 3) & 1) << 3);
      int gg = ge0 + (lane >> 4);
      ldsm_x4(a[mi], vb + tok * 128 + ((gg ^ (tok & 7)) << 4));
    }
#pragma unroll
    for (int dj = 0; dj < 4; ++dj) {
      int d = wd * 32 + dj * 8 + (lane & 7);
      int gg = ge0 + ((lane >> 3) & 1);
      ldsm_x2(bf[dj], ab + d * 128 + ((gg ^ (d & 7)) << 4));
    }
#pragma unroll
    for (int mi = 0; mi < 4; ++mi)
#pragma unroll
      for (int dj = 0; dj < 4; ++dj)
        mma_f16(acc[mi][dj], a[mi], bf[dj][0], bf[dj][1]);
  }

  const int rr = lane >> 2, cc2 = (lane & 3) * 2;
#pragma unroll
  for (int mi = 0; mi < 4; ++mi) {
    size_t tok = (size_t)(b * NN + tb + wm * 64 + mi * 16 + rr);
#pragma unroll
    for (int dj = 0; dj < 4; ++dj) {
      size_t col = h * DH + wd * 32 + dj * 8 + cc2;
      *(__half2*)(g_Zh + tok * CC + col) =
          __floats2half2_rn(acc[mi][dj][0], acc[mi][dj][1]);
      *(__half2*)(g_Zh + (tok + 8) * CC + col) =
          __floats2half2_rn(acc[mi][dj][2], acc[mi][dj][3]);
    }
  }
}

// ---------------------------------------------------------------------------
extern "C" void kernel_launch(void* const* d_in, const int* in_sizes, int n_in,
                              void* d_out, int out_size) {
  const float* x      = (const float*)d_in[0];
  const float* w_qkv  = (const float*)d_in[1];
  const float* temp   = (const float*)d_in[2];
  const float* w_proj = (const float*)d_in[3];
  const float* b_proj = (const float*)d_in[4];
  float* out = (float*)d_out;

  static __half *Yh = nullptr, *Ah = nullptr, *Wh = nullptr, *Zh = nullptr;
  if (Yh == nullptr) {
    cudaGetSymbolAddress((void**)&Yh, g_Yh);
    cudaGetSymbolAddress((void**)&Zh, g_Zh);
    cudaGetSymbolAddress((void**)&Ah, g_Af16);
    cudaGetSymbolAddress((void**)&Wh, g_Wf16);
    cudaFuncSetAttribute((const void*)hgemm<1, 1>,
                         cudaFuncAttributeMaxDynamicSharedMemorySize, HGEMM_SMEM);
    cudaFuncSetAttribute((const void*)hgemm<0, 0>,
                         cudaFuncAttributeMaxDynamicSharedMemorySize, HGEMM_SMEM);
    cudaFuncSetAttribute((const void*)gramsm_kernel,
                         cudaFuncAttributeMaxDynamicSharedMemorySize, GRSM_SMEM);
  }

  // prep
  f2h_kernel<<<(size_t)M_ROWS * CC / 2048, 256>>>(x, Ah);
  wtrans_kernel<<<dim3(QKV_COLS / 32, CC / 32), 256>>>(w_qkv, Wh, CC, QKV_COLS);

  // K1: qkv = x @ w_qkv -> fp16 Yh, + sumsq partials
  hgemm<1, 1><<<dim3(QKV_COLS / 128, M_ROWS / 128), 256, HGEMM_SMEM>>>(
      Ah, Wh, Yh, nullptr, QKV_COLS, CC);

  sumsq_reduce<<<dim3(8, BB), 256>>>();
  gramsm_kernel<<<BB * HH, 256, GRSM_SMEM>>>(temp);
  attnv_tc_kernel<<<dim3(NN / 256, BB * HH), 256>>>();

  // K5
  wtrans_kernel<<<dim3(CC / 32, CC / 32), 256>>>(w_proj, Wh, CC, CC);
  hgemm<0, 0><<<dim3(CC / 128, M_ROWS / 128), 256, HGEMM_SMEM>>>(
      Zh, Wh, out, b_proj, CC, CC);
}